// round 11
// baseline (speedup 1.0000x reference)
#include <cuda_runtime.h>
#include <cuda_bf16.h>
#include <cstdint>

#define ND 768
#define SZ (768*768)
#define MNTOT SZ
typedef long long ll;

// ---------------- scratch (device globals) ----------------------------------
__device__ float g_Tf[10*SZ];                         // fp32 T[side][k]
__device__ __align__(16) __nv_bfloat16 g_Tsh[10*SZ];  // split hi
__device__ __align__(16) __nv_bfloat16 g_Tsl[10*SZ];  // split lo
__device__ __align__(16) __nv_bfloat16 g_xTh[SZ];
__device__ __align__(16) __nv_bfloat16 g_xTl[SZ];
__device__ float g_Yf[4*SZ];                          // Y_1..Y_4 fp32
__device__ __align__(16) __nv_bfloat16 g_Ysh[5*SZ];   // slot0 = x split; 1..4 = Y_i
__device__ __align__(16) __nv_bfloat16 g_Ysl[5*SZ];
__device__ float g_bff[20*SZ];
__device__ __align__(16) __nv_bfloat16 g_hh[32*SZ];   // h point-major [pt][32] hi
__device__ __align__(16) __nv_bfloat16 g_hl[32*SZ];   // lo
__device__ float g_c[32*SZ];                          // c point-major [pt][32]
__device__ __align__(16) __nv_bfloat16 g_Wth[128*64]; // [n=g*32+o][k] hi
__device__ __align__(16) __nv_bfloat16 g_Wtl[128*64]; // lo

// ---------------- helpers -----------------------------------------------------
#define SWZ(x)   ((x) ^ (((x) >> 3) & 0x70))   // 128B rows
#define SWZ64(x) ((x) ^ (((x) >> 3) & 0x30))   // 64B rows

template<int KC>
__device__ __forceinline__ uint32_t swzk(uint32_t x) {
  return (KC == 64) ? SWZ(x) : SWZ64(x);
}

__device__ __forceinline__ uint32_t smem_u32(const void* p) {
  uint32_t a;
  asm("{ .reg .u64 t; cvta.to.shared.u64 t, %1; cvt.u32.u64 %0, t; }"
      : "=r"(a) : "l"(p));
  return a;
}

__device__ __forceinline__ void cpa16(uint32_t dst, const void* src) {
  asm volatile("cp.async.cg.shared.global [%0], [%1], 16;"
               :: "r"(dst), "l"(src) : "memory");
}
__device__ __forceinline__ void cpa16_ca(uint32_t dst, const void* src) {
  asm volatile("cp.async.ca.shared.global [%0], [%1], 16;"
               :: "r"(dst), "l"(src) : "memory");
}
#define CP_COMMIT() asm volatile("cp.async.commit_group;" ::: "memory")
#define CP_WAIT(n)  asm volatile("cp.async.wait_group %0;" :: "n"(n) : "memory")

__device__ __forceinline__ void ldm4(uint32_t* r, uint32_t addr) {
  asm volatile("ldmatrix.sync.aligned.m8n8.x4.shared.b16 {%0,%1,%2,%3}, [%4];"
               : "=r"(r[0]), "=r"(r[1]), "=r"(r[2]), "=r"(r[3]) : "r"(addr));
}

__device__ __forceinline__ void mma16816(float* c, const uint32_t* a,
                                         const uint32_t* b) {
  asm volatile(
      "mma.sync.aligned.m16n8k16.row.col.f32.bf16.bf16.f32 "
      "{%0,%1,%2,%3},{%4,%5,%6,%7},{%8,%9},{%0,%1,%2,%3};"
      : "+f"(c[0]), "+f"(c[1]), "+f"(c[2]), "+f"(c[3])
      : "r"(a[0]), "r"(a[1]), "r"(a[2]), "r"(a[3]), "r"(b[0]), "r"(b[1]));
}

__device__ __forceinline__ uint32_t pack2(__nv_bfloat16 a, __nv_bfloat16 b) {
  __nv_bfloat162 t(a, b);
  return *reinterpret_cast<uint32_t*>(&t);
}

// load one KC-wide K chunk of 4 matrices (Ah[TM],Al[TM],Bh[128],Bl[128])
template<int TM, int KC>
__device__ __forceinline__ void load_chunk(
    uint32_t sb, int s, int kc, int tid, int brow, int bcol,
    const __nv_bfloat16* a0, const __nv_bfloat16* a1,
    const __nv_bfloat16* b0, const __nv_bfloat16* b1)
{
  constexpr int ROWB   = KC * 2;
  constexpr int ASTAGE = TM * ROWB;
  constexpr int BSTAGE = 128 * ROWB;
  constexpr int STAGE  = 2 * ASTAGE + 2 * BSTAGE;
  constexpr int CPR    = KC / 8;
  constexpr int ITER   = (2 * TM + 256) * CPR / 256;
#pragma unroll
  for (int i = 0; i < ITER; i++) {
    int idx = tid + i * 256;
    int cc = idx % CPR;
    int rowIdx = idx / CPR;
    const __nv_bfloat16* src;
    uint32_t dstbase;
    if (rowIdx < 2 * TM) {
      int mat = rowIdx / TM;
      int row = rowIdx % TM;
      src = (mat ? a1 : a0) + (ll)(brow + row) * ND + kc * KC + cc * 8;
      dstbase = mat * ASTAGE + swzk<KC>(row * ROWB + cc * 16);
    } else {
      int rr = rowIdx - 2 * TM;
      int mat = rr >> 7;
      int row = rr & 127;
      src = (mat ? b1 : b0) + (ll)(bcol + row) * ND + kc * KC + cc * 8;
      dstbase = 2 * ASTAGE + mat * BSTAGE + swzk<KC>(row * ROWB + cc * 16);
    }
    cpa16(sb + s * STAGE + dstbase, src);
  }
}

// ---------------- tensor-core GEMM: C = alpha*A@B~^T + beta*Cin --------------
// TMx128 tile, KC chunk, NS-stage cp.async ring, 1 sync per chunk.
template<int TM, int KC, int NS>
__global__ __launch_bounds__(256, 2) void tc_gemm(
    const __nv_bfloat16* __restrict__ Ah, const __nv_bfloat16* __restrict__ Al,
    const __nv_bfloat16* __restrict__ Bh, const __nv_bfloat16* __restrict__ Bl,
    const float* __restrict__ Cin, float* __restrict__ Cout,
    __nv_bfloat16* __restrict__ Couth, __nv_bfloat16* __restrict__ Coutl,
    ll sAz, ll sAdiv, int adiv,
    ll sBz, ll sBmod, int bmod,
    ll sCinz, ll sCz, float alpha, float beta, int cinmode)
{
  extern __shared__ char dsm[];
  constexpr int ROWB   = KC * 2;
  constexpr int ASTAGE = TM * ROWB;
  constexpr int BSTAGE = 128 * ROWB;
  constexpr int STAGE  = 2 * ASTAGE + 2 * BSTAGE;
  constexpr int NCHUNK = ND / KC;
  constexpr int NSTEP  = KC / 16;
  constexpr int NI = (TM == 128) ? 8 : 4;
  constexpr int NPAIR = NI / 4;

  int z = blockIdx.z;
  ll offA = sAz * z + sAdiv * (z / adiv);
  ll offB = sBz * z + sBmod * (z % bmod);
  const __nv_bfloat16* ah = Ah + offA;
  const __nv_bfloat16* al = Al + offA;
  const __nv_bfloat16* bh = Bh + offB;
  const __nv_bfloat16* bl = Bl + offB;
  const int brow = blockIdx.y * TM;
  const int bcol = blockIdx.x * 128;

  int tid = threadIdx.x;
  int lane = tid & 31;
  int wid = tid >> 5;
  int wrow, wcol;
  if (TM == 128) { wrow = (wid & 3) * 32; wcol = (wid >> 2) * 64; }
  else           { wrow = (wid & 1) * 32; wcol = (wid >> 1) * 32; }

  uint32_t raw = smem_u32(dsm);
  uint32_t sb = (raw + 1023) & ~1023u;

  float acc[2][NI][4];
#pragma unroll
  for (int mi = 0; mi < 2; mi++)
#pragma unroll
    for (int ni = 0; ni < NI; ni++)
#pragma unroll
      for (int e = 0; e < 4; e++) acc[mi][ni][e] = 0.0f;

  int a_r  = (lane & 7) + ((lane >> 3) & 1) * 8;
  int a_k8 = ((lane >> 4) & 1) * 8;
  int b_r  = (lane & 7) + ((lane >> 4) & 1) * 8;
  int b_k8 = ((lane >> 3) & 1) * 8;

#pragma unroll
  for (int p = 0; p < NS - 1; p++) {
    load_chunk<TM,KC>(sb, p, p, tid, brow, bcol, ah, al, bh, bl);
    CP_COMMIT();
  }

  for (int kc = 0; kc < NCHUNK; kc++) {
    if (kc < NCHUNK - 1) { CP_WAIT(NS - 2); } else { CP_WAIT(0); }
    __syncthreads();

    uint32_t st  = sb + (kc % NS) * STAGE;
    uint32_t tAh = st;
    uint32_t tAl = st + ASTAGE;
    uint32_t tBh = st + 2 * ASTAGE;
    uint32_t tBl = tBh + BSTAGE;

#pragma unroll
    for (int s = 0; s < NSTEP; s++) {
      uint32_t fah[2][4], fal[2][4];
#pragma unroll
      for (int mi = 0; mi < 2; mi++) {
        int r = wrow + mi * 16 + a_r;
        uint32_t off = swzk<KC>(r * ROWB + (s * 16 + a_k8) * 2);
        ldm4(fah[mi], tAh + off);
        ldm4(fal[mi], tAl + off);
      }
#pragma unroll
      for (int p = 0; p < NPAIR; p++) {
        uint32_t fbh[4][2], fbl[4][2];
#pragma unroll
        for (int nj2 = 0; nj2 < 2; nj2++) {
          int r = wcol + (p * 2 + nj2) * 16 + b_r;
          uint32_t off = swzk<KC>(r * ROWB + (s * 16 + b_k8) * 2);
          uint32_t t4[4];
          ldm4(t4, tBh + off);
          fbh[nj2 * 2][0] = t4[0]; fbh[nj2 * 2][1] = t4[1];
          fbh[nj2 * 2 + 1][0] = t4[2]; fbh[nj2 * 2 + 1][1] = t4[3];
          ldm4(t4, tBl + off);
          fbl[nj2 * 2][0] = t4[0]; fbl[nj2 * 2][1] = t4[1];
          fbl[nj2 * 2 + 1][0] = t4[2]; fbl[nj2 * 2 + 1][1] = t4[3];
        }
#pragma unroll
        for (int mi = 0; mi < 2; mi++)
#pragma unroll
          for (int nl = 0; nl < 4; nl++)
            mma16816(acc[mi][p * 4 + nl], fah[mi], fbh[nl]);
#pragma unroll
        for (int mi = 0; mi < 2; mi++)
#pragma unroll
          for (int nl = 0; nl < 4; nl++)
            mma16816(acc[mi][p * 4 + nl], fah[mi], fbl[nl]);
#pragma unroll
        for (int mi = 0; mi < 2; mi++)
#pragma unroll
          for (int nl = 0; nl < 4; nl++)
            mma16816(acc[mi][p * 4 + nl], fal[mi], fbh[nl]);
      }
    }

    if (kc + NS - 1 < NCHUNK) {
      load_chunk<TM,KC>(sb, (kc + NS - 1) % NS, kc + NS - 1, tid, brow, bcol,
                        ah, al, bh, bl);
      CP_COMMIT();
    }
  }

  const float* cinp = (cinmode == 2) ? (Cin + sCinz * z) : (const float*)0;
  float* co = Cout ? (Cout + sCz * z) : (float*)0;
  __nv_bfloat16* coh = Couth ? (Couth + sCz * z) : (__nv_bfloat16*)0;
  __nv_bfloat16* col = Coutl ? (Coutl + sCz * z) : (__nv_bfloat16*)0;
  int qr = lane >> 2, qc = lane & 3;

#pragma unroll
  for (int mi = 0; mi < 2; mi++) {
#pragma unroll
    for (int ni = 0; ni < NI; ni++) {
      int gr0 = brow + wrow + mi * 16 + qr;
      int gc  = bcol + wcol + ni * 8 + qc * 2;
      float2 v0, v1;
      v0.x = alpha * acc[mi][ni][0];
      v0.y = alpha * acc[mi][ni][1];
      v1.x = alpha * acc[mi][ni][2];
      v1.y = alpha * acc[mi][ni][3];
      if (cinmode == 2) {
        float2 c0 = *(const float2*)&cinp[(ll)gr0 * ND + gc];
        float2 c1 = *(const float2*)&cinp[(ll)(gr0 + 8) * ND + gc];
        v0.x += beta * c0.x; v0.y += beta * c0.y;
        v1.x += beta * c1.x; v1.y += beta * c1.y;
      } else if (cinmode == 1) {
        if (gr0 == gc)         v0.x += beta;
        if (gr0 == gc + 1)     v0.y += beta;
        if (gr0 + 8 == gc)     v1.x += beta;
        if (gr0 + 8 == gc + 1) v1.y += beta;
      }
      if (co) {
        *(float2*)&co[(ll)gr0 * ND + gc]       = v0;
        *(float2*)&co[(ll)(gr0 + 8) * ND + gc] = v1;
      }
      if (coh) {
        __nv_bfloat16 h0 = __float2bfloat16(v0.x);
        __nv_bfloat16 h1 = __float2bfloat16(v0.y);
        __nv_bfloat16 h2 = __float2bfloat16(v1.x);
        __nv_bfloat16 h3 = __float2bfloat16(v1.y);
        *(uint32_t*)&coh[(ll)gr0 * ND + gc]       = pack2(h0, h1);
        *(uint32_t*)&coh[(ll)(gr0 + 8) * ND + gc] = pack2(h2, h3);
        *(uint32_t*)&col[(ll)gr0 * ND + gc] =
            pack2(__float2bfloat16(v0.x - __bfloat162float(h0)),
                  __float2bfloat16(v0.y - __bfloat162float(h1)));
        *(uint32_t*)&col[(ll)(gr0 + 8) * ND + gc] =
            pack2(__float2bfloat16(v1.x - __bfloat162float(h2)),
                  __float2bfloat16(v1.y - __bfloat162float(h3)));
      }
    }
  }
}

// ---------------- merged setup (single launch; replaces memcpys/splits) ------
// z=0: L_row -> Tf+S (fp32) + Tsh/Tsl+S      z=1: L_col -> Tf+6S + splits
// z=2: x -> xcur (fp32) + Ysh/Ysl slot0      z=3: W/U split (32 blocks)
// z=4: x -> xTh/xTl (transpose split)
__global__ __launch_bounds__(256) void setup_kernel(
    const float* __restrict__ L_row, const float* __restrict__ L_col,
    float* __restrict__ Tf, __nv_bfloat16* __restrict__ Tsh,
    __nv_bfloat16* __restrict__ Tsl,
    const float* __restrict__ x, float* __restrict__ xcur,
    __nv_bfloat16* __restrict__ Ysh, __nv_bfloat16* __restrict__ Ysl,
    __nv_bfloat16* __restrict__ xTh, __nv_bfloat16* __restrict__ xTl,
    const float* __restrict__ Wf, const float* __restrict__ Uf,
    const float* __restrict__ Wi, const float* __restrict__ Ui,
    const float* __restrict__ Wo, const float* __restrict__ Uo,
    const float* __restrict__ Wc, const float* __restrict__ Uc,
    __nv_bfloat16* __restrict__ Wth, __nv_bfloat16* __restrict__ Wtl)
{
  __shared__ float ts[32][33];
  int z = blockIdx.z;
  int t = threadIdx.x;

  if (z == 3) {                        // W/U split
    if (blockIdx.x >= 32) return;
    const float* Ws[4] = {Wf, Wi, Wo, Wc};
    const float* Us[4] = {Uf, Ui, Uo, Uc};
    int idx = blockIdx.x * 256 + t;    // 0..8191
    int n = idx >> 6, k = idx & 63;
    int g = n >> 5, o = n & 31;
    float v = (k < 32) ? Ws[g][k * 32 + o] : Us[g][(k - 32) * 32 + o];
    __nv_bfloat16 vh = __float2bfloat16(v);
    Wth[idx] = vh;
    Wtl[idx] = __float2bfloat16(v - __bfloat162float(vh));
    return;
  }
  if (z == 4) {                        // transpose split of x (576 = 24x24)
    int bx = (blockIdx.x % 24) * 32, by = (blockIdx.x / 24) * 32;
    int tx = t & 31, ty = t >> 5;      // 32 x 8
#pragma unroll
    for (int i = 0; i < 4; i++)
      ts[ty + 8 * i][tx] = x[(ll)(by + ty + 8 * i) * ND + bx + tx];
    __syncthreads();
#pragma unroll
    for (int i = 0; i < 4; i++) {
      float a = ts[tx][ty + 8 * i];
      __nv_bfloat16 h = __float2bfloat16(a);
      ll o = (ll)(bx + ty + 8 * i) * ND + by + tx;
      xTh[o] = h;
      xTl[o] = __float2bfloat16(a - __bfloat162float(h));
    }
    return;
  }

  const float* src;
  float* fdst;
  __nv_bfloat16 *hi, *lo;
  if (z == 0)      { src = L_row; fdst = Tf + (ll)SZ;     hi = Tsh + (ll)SZ;     lo = Tsl + (ll)SZ; }
  else if (z == 1) { src = L_col; fdst = Tf + (ll)6 * SZ; hi = Tsh + (ll)6 * SZ; lo = Tsl + (ll)6 * SZ; }
  else             { src = x;     fdst = xcur;            hi = Ysh;              lo = Ysl; }

  int idx = blockIdx.x * 256 + t;      // over SZ/4
  float4 v = *(const float4*)(src + (ll)idx * 4);
  *(float4*)(fdst + (ll)idx * 4) = v;
  float a[4] = {v.x, v.y, v.z, v.w};
  __nv_bfloat16 h[4], l[4];
#pragma unroll
  for (int e = 0; e < 4; e++) {
    h[e] = __float2bfloat16(a[e]);
    l[e] = __float2bfloat16(a[e] - __bfloat162float(h[e]));
  }
  uint2 uh, ul;
  uh.x = pack2(h[0], h[1]); uh.y = pack2(h[2], h[3]);
  ul.x = pack2(l[0], l[1]); ul.y = pack2(l[2], l[3]);
  *(uint2*)(hi + (ll)idx * 4) = uh;
  *(uint2*)(lo + (ll)idx * 4) = ul;
}

// ---------------- fused_rnn v5: + transposed x-split in epilogue -------------
__device__ __forceinline__ float sigf(float v) {
  return __fdividef(1.0f, 1.0f + __expf(-v));
}

__global__ __launch_bounds__(256, 2) void fused_rnn(
    const float* __restrict__ Yf_g, const float* __restrict__ bff_g,
    const float* __restrict__ theta, const float* __restrict__ bias,
    const __nv_bfloat16* __restrict__ Wth, const __nv_bfloat16* __restrict__ Wtl,
    const float* __restrict__ bf_, const float* __restrict__ bi_,
    const float* __restrict__ bo_, const float* __restrict__ bc_,
    const float* __restrict__ Wout, const float* __restrict__ bout,
    float* c, __nv_bfloat16* hh_g, __nv_bfloat16* hl_g, float* x,
    __nv_bfloat16* __restrict__ xsh, __nv_bfloat16* __restrict__ xsl,
    __nv_bfloat16* __restrict__ xTh, __nv_bfloat16* __restrict__ xTl,
    int first, int last)
{
  extern __shared__ char dsm[];
  uint32_t raw = smem_u32(dsm);
  uint32_t sb = (raw + 1023) & ~1023u;
  char* base = dsm + (sb - raw);

  float* th  = (float*)(base + 65536);            // 800
  float* bs  = (float*)(base + 65536 + 3200);     // 32
  float* swo = (float*)(base + 65536 + 3328);     // 32
  float* sbg = (float*)(base + 65536 + 3456);     // 128

  int t = threadIdx.x;
  int lane = t & 31;
  int w = t >> 5;
  size_t bpt = (size_t)blockIdx.x * 128;

  // ---- issue cp.async: W tiles (.ca) + h rows --------------------------------
#pragma unroll
  for (int i = 0; i < 8; i++) {
    int idx = t + i * 256;
    int mat = idx >> 10;
    int rr  = (idx >> 3) & 127;
    int c4  = idx & 7;
    const __nv_bfloat16* src = (mat ? Wtl : Wth) + rr * 64 + c4 * 8;
    cpa16_ca(sb + 32768 + mat * 16384 + SWZ(rr * 128 + c4 * 16), src);
  }
  if (!first) {
#pragma unroll
    for (int i = 0; i < 8; i++) {
      int idx = t + i * 256;
      int mat = idx >> 10;
      int rr  = (idx >> 2) & 127;
      int c4h = (idx & 3) + 4;
      const __nv_bfloat16* src =
          (mat ? hl_g : hh_g) + (bpt + rr) * 32 + (c4h - 4) * 8;
      cpa16(sb + mat * 16384 + SWZ(rr * 128 + c4h * 16), src);
    }
  } else {
    uint4 z4 = make_uint4(0, 0, 0, 0);
#pragma unroll
    for (int i = 0; i < 8; i++) {
      int idx = t + i * 256;
      int mat = idx >> 10;
      int rr  = (idx >> 2) & 127;
      int c4h = (idx & 3) + 4;
      *(uint4*)(base + mat * 16384 + SWZ(rr * 128 + c4h * 16)) = z4;
    }
  }
  CP_COMMIT();

  // ---- prefetch 25 conv-source values (fp32; before any sync) ----------------
  int r   = t & 127;
  int ohp = (t >> 7) * 16;
  size_t rg = bpt + r;
  float v[25];
  v[0] = __ldg(x + rg);
#pragma unroll
  for (int i = 1; i < 5; i++)
    v[i * 5] = __ldg(Yf_g + (ll)(i - 1) * SZ + rg);
#pragma unroll
  for (int i = 0; i < 5; i++)
#pragma unroll
    for (int j = 1; j < 5; j++)
      v[i * 5 + j] = __ldg(bff_g + (ll)(i * 4 + j - 1) * SZ + rg);

  // ---- scalars ---------------------------------------------------------------
  for (int i = t; i < 800; i += 256) th[i] = theta[i];
  if (t < 32) { bs[t] = bias[t]; swo[t] = Wout[t]; }
  if (t < 128) { const float* bx[4] = {bf_, bi_, bo_, bc_}; sbg[t] = bx[t >> 5][t & 31]; }
  __syncthreads();

  // ---- combine -> A cols 0..31 (xc split bf16) -------------------------------
  {
    float out[16];
#pragma unroll
    for (int o = 0; o < 16; o++) out[o] = bs[ohp + o];
#pragma unroll
    for (int ij = 0; ij < 25; ij++) {
      const float* tw = &th[ij * 32 + ohp];
#pragma unroll
      for (int o = 0; o < 16; o++) out[o] += v[ij] * tw[o];
    }
#pragma unroll
    for (int i = 0; i < 8; i++) {
      float a0 = out[2 * i], a1 = out[2 * i + 1];
      __nv_bfloat16 h0 = __float2bfloat16(a0);
      __nv_bfloat16 h1 = __float2bfloat16(a1);
      uint32_t byte = r * 128 + (ohp + 2 * i) * 2;
      *(uint32_t*)(base + SWZ(byte)) = pack2(h0, h1);
      *(uint32_t*)(base + 16384 + SWZ(byte)) =
          pack2(__float2bfloat16(a0 - __bfloat162float(h0)),
                __float2bfloat16(a1 - __bfloat162float(h1)));
    }
  }
  CP_WAIT(0);
  __syncthreads();

  // ---- HMMA: PRE[128 pt x 128 n] = A @ W^T (3-term split) --------------------
  int a_r  = (lane & 7) + ((lane >> 3) & 1) * 8;
  int a_k8 = ((lane >> 4) & 1) * 8;
  int b_r  = (lane & 7) + ((lane >> 4) & 1) * 8;
  int b_k8 = ((lane >> 3) & 1) * 8;

  float acc[16][4];
#pragma unroll
  for (int nt = 0; nt < 16; nt++)
#pragma unroll
    for (int e = 0; e < 4; e++) acc[nt][e] = 0.0f;

#pragma unroll
  for (int ks = 0; ks < 4; ks++) {
    uint32_t abyte = SWZ((w * 16 + a_r) * 128 + (ks * 16 + a_k8) * 2);
    uint32_t ah4[4], al4[4];
    ldm4(ah4, sb + abyte);
    ldm4(al4, sb + 16384 + abyte);
#pragma unroll
    for (int np = 0; np < 8; np++) {
      uint32_t bbyte = SWZ((np * 16 + b_r) * 128 + (ks * 16 + b_k8) * 2);
      uint32_t bh4[4], bl4[4];
      ldm4(bh4, sb + 32768 + bbyte);
      ldm4(bl4, sb + 49152 + bbyte);
      mma16816(acc[2 * np],     ah4, bh4);
      mma16816(acc[2 * np + 1], ah4, bh4 + 2);
      mma16816(acc[2 * np],     ah4, bl4);
      mma16816(acc[2 * np + 1], ah4, bl4 + 2);
      mma16816(acc[2 * np],     al4, bh4);
      mma16816(acc[2 * np + 1], al4, bh4 + 2);
    }
  }

  // ---- in-register gates + c/h update + dx partials --------------------------
  int qr = lane >> 2, qc = lane & 3;
  size_t p0 = bpt + w * 16 + qr;
  float pd[2] = {0.0f, 0.0f};

#pragma unroll
  for (int m = 0; m < 4; m++) {
#pragma unroll
    for (int rh = 0; rh < 2; rh++) {
      size_t pt = p0 + 8 * rh;
      int ob = 8 * m + 2 * qc;
      float2 cold = make_float2(0.0f, 0.0f);
      if (!first) cold = *(const float2*)&c[pt * 32 + ob];
      float cn[2], hn[2];
#pragma unroll
      for (int p = 0; p < 2; p++) {
        int o = ob + p;
        int e = p + 2 * rh;
        float zi = acc[4 + m][e]  + sbg[32 + o];
        float zc = acc[12 + m][e] + sbg[96 + o];
        float cnew = sigf(zi) * sigf(zc);
        if (!first) {
          float zf = acc[m][e] + sbg[o];
          cnew += sigf(zf) * (p ? cold.y : cold.x);
        }
        cn[p] = cnew;
        pd[rh] += cnew * swo[o];
        if (!last) {
          float zo = acc[8 + m][e] + sbg[64 + o];
          hn[p] = sigf(zo) * sigf(cnew);
        }
      }
      if (!last) {
        *(float2*)&c[pt * 32 + ob] = make_float2(cn[0], cn[1]);
        __nv_bfloat16 h0 = __float2bfloat16(hn[0]);
        __nv_bfloat16 h1 = __float2bfloat16(hn[1]);
        *(uint32_t*)&hh_g[pt * 32 + ob] = pack2(h0, h1);
        *(uint32_t*)&hl_g[pt * 32 + ob] =
            pack2(__float2bfloat16(hn[0] - __bfloat162float(h0)),
                  __float2bfloat16(hn[1] - __bfloat162float(h1)));
      }
    }
  }

#pragma unroll
  for (int rh = 0; rh < 2; rh++) {
    pd[rh] += __shfl_xor_sync(0xFFFFFFFF, pd[rh], 1);
    pd[rh] += __shfl_xor_sync(0xFFFFFFFF, pd[rh], 2);
  }
  if (qc == 0) {
    float b0 = __ldg(bout);
#pragma unroll
    for (int rh = 0; rh < 2; rh++) {
      size_t gi = p0 + 8 * rh;
      float xn = x[gi] + tanhf(pd[rh] + b0);
      x[gi] = xn;
      if (!last) {
        __nv_bfloat16 xh2 = __float2bfloat16(xn);
        __nv_bfloat16 xl2 = __float2bfloat16(xn - __bfloat162float(xh2));
        xsh[gi] = xh2;
        xsl[gi] = xl2;
        // transposed split for next iteration's Y-GEMM B operand
        int row = (int)(gi / ND);
        int col = (int)(gi - (size_t)row * ND);
        xTh[(ll)col * ND + row] = xh2;
        xTl[(ll)col * ND + row] = xl2;
      }
    }
  }
}

// ---------------- orchestration ----------------------------------------------
extern "C" void kernel_launch(void* const* d_in, const int* in_sizes, int n_in,
                              void* d_out, int out_size)
{
  const float* x     = (const float*)d_in[0];
  const float* L_row = (const float*)d_in[1];
  const float* L_col = (const float*)d_in[2];
  const float* theta = (const float*)d_in[3];
  const float* bias  = (const float*)d_in[4];
  const float* W_f = (const float*)d_in[5];
  const float* U_f = (const float*)d_in[6];
  const float* b_f = (const float*)d_in[7];
  const float* W_i = (const float*)d_in[8];
  const float* U_i = (const float*)d_in[9];
  const float* b_i = (const float*)d_in[10];
  const float* W_o = (const float*)d_in[11];
  const float* U_o = (const float*)d_in[12];
  const float* b_o = (const float*)d_in[13];
  const float* W_c = (const float*)d_in[14];
  const float* U_c = (const float*)d_in[15];
  const float* b_c = (const float*)d_in[16];
  const float* W_out = (const float*)d_in[17];
  const float* b_out = (const float*)d_in[18];
  // d_in[19] = nb_iterations_rnn = 3 (fixed by setup)

  float* xcur = (float*)d_out;

  float *Tf, *Yf, *bff, *c;
  __nv_bfloat16 *Tsh, *Tsl, *xTh, *xTl, *Ysh, *Ysl, *hh, *hl, *Wth, *Wtl;
  cudaGetSymbolAddress((void**)&Tf,  g_Tf);
  cudaGetSymbolAddress((void**)&Tsh, g_Tsh);
  cudaGetSymbolAddress((void**)&Tsl, g_Tsl);
  cudaGetSymbolAddress((void**)&xTh, g_xTh);
  cudaGetSymbolAddress((void**)&xTl, g_xTl);
  cudaGetSymbolAddress((void**)&Yf,  g_Yf);
  cudaGetSymbolAddress((void**)&Ysh, g_Ysh);
  cudaGetSymbolAddress((void**)&Ysl, g_Ysl);
  cudaGetSymbolAddress((void**)&bff, g_bff);
  cudaGetSymbolAddress((void**)&hh,  g_hh);
  cudaGetSymbolAddress((void**)&hl,  g_hl);
  cudaGetSymbolAddress((void**)&c,   g_c);
  cudaGetSymbolAddress((void**)&Wth, g_Wth);
  cudaGetSymbolAddress((void**)&Wtl, g_Wtl);

  const ll S = SZ;
  const int DSM_CHEB = 1024 + 3 * 49152;   // TM=64, KC=64, 3-stage
  const int DSM_Y    = 1024 + 4 * 24576;   // TM=64, KC=32, 4-stage
  const int DSM_BF   = 1024 + 3 * 32768;   // TM=128, KC=32, 3-stage
  const int FSM      = 1024 + 65536 + 3968;
  cudaFuncSetAttribute((const void*)tc_gemm<64,64,3>,  cudaFuncAttributeMaxDynamicSharedMemorySize, DSM_CHEB);
  cudaFuncSetAttribute((const void*)tc_gemm<64,32,4>,  cudaFuncAttributeMaxDynamicSharedMemorySize, DSM_Y);
  cudaFuncSetAttribute((const void*)tc_gemm<128,32,3>, cudaFuncAttributeMaxDynamicSharedMemorySize, DSM_BF);
  cudaFuncSetAttribute((const void*)fused_rnn,         cudaFuncAttributeMaxDynamicSharedMemorySize, FSM);

  // launch 1: merged setup (L splits + fp32 copies, x copy+split, W/U, x^T)
  {
    dim3 g(SZ / 1024, 1, 5);
    setup_kernel<<<g, 256>>>(L_row, L_col, Tf, Tsh, Tsl,
                             x, xcur, Ysh, Ysl, xTh, xTl,
                             W_f, U_f, W_i, U_i, W_o, U_o, W_c, U_c, Wth, Wtl);
  }

  // launches 2-4: Chebyshev recursion (epilogue emits fp32 + split)
  for (int k = 2; k <= 4; k++) {
    dim3 g(6, 12, 2);
    int cinmode = (k == 2) ? 1 : 2;
    const float* cin = (k == 2) ? (const float*)0 : (Tf + (ll)(k - 2) * S);
    tc_gemm<64,64,3><<<g, 256, DSM_CHEB>>>(
        Tsh + S, Tsl + S,
        Tsh + (ll)(k - 1) * S, Tsl + (ll)(k - 1) * S,
        cin, Tf + (ll)k * S, Tsh + (ll)k * S, Tsl + (ll)k * S,
        5 * S, 0, 1,
        5 * S, 0, 1,
        5 * S, 5 * S, 2.0f, -1.0f, cinmode);
  }

  for (int it = 0; it < 3; it++) {
    // Y_{1+z} = Tr_{1+z} @ x   (launch 5 on iter 0)
    {
      dim3 g(6, 12, 4);
      tc_gemm<64,32,4><<<g, 256, DSM_Y>>>(
          Tsh + S, Tsl + S, xTh, xTl,
          (const float*)0, Yf, Ysh + S, Ysl + S,
          S, 0, 1,    0, 0, 1,
          0, S, 1.0f, 0.0f, 0);
    }
    // bf[z] = Y_{z/4} @ Tc_{1+z%4}   (launch 6 on iter 0 -> ncu capture)
    {
      dim3 g(6, 6, 20);
      tc_gemm<128,32,3><<<g, 256, DSM_BF>>>(
          Ysh, Ysl, Tsh + 6 * S, Tsl + 6 * S,
          (const float*)0, bff, (__nv_bfloat16*)0, (__nv_bfloat16*)0,
          0, S, 4,    0, S, 4,
          0, S, 1.0f, 0.0f, 0);
    }
    fused_rnn<<<SZ / 128, 256, FSM>>>(
        Yf, bff, theta, bias, Wth, Wtl,
        b_f, b_i, b_o, b_c, W_out, b_out,
        c, hh, hl, xcur, Ysh, Ysl, xTh, xTl,
        (it == 0) ? 1 : 0, (it == 2) ? 1 : 0);
  }
}

// round 12
// speedup vs baseline: 1.3790x; 1.3790x over previous
#include <cuda_runtime.h>
#include <cuda_bf16.h>
#include <cuda_fp16.h>
#include <cstdint>

#define ND 768
#define SZ (768*768)
#define MNTOT SZ
typedef long long ll;

// ---------------- scratch (device globals) ----------------------------------
__device__ float g_Tf[10*SZ];                         // fp32 T[side][k]
__device__ __align__(16) __nv_bfloat16 g_Tsh[10*SZ];  // split hi (cheb)
__device__ __align__(16) __nv_bfloat16 g_Tsl[10*SZ];  // split lo (cheb)
__device__ __align__(16) __half g_Tf16[10*SZ];        // fp16 T (Y/bf operands)
__device__ __align__(16) __half g_xT16[SZ];           // fp16 x^T
__device__ float g_Yf[4*SZ];                          // Y_1..Y_4 fp32
__device__ __align__(16) __half g_Y16[5*SZ];          // slot0 = x fp16; 1..4 = Y_i
__device__ float g_bff[20*SZ];
__device__ __align__(16) __nv_bfloat16 g_hh[32*SZ];   // h point-major [pt][32] hi
__device__ __align__(16) __nv_bfloat16 g_hl[32*SZ];   // lo
__device__ float g_c[32*SZ];                          // c point-major [pt][32]
__device__ __align__(16) __nv_bfloat16 g_Wth[128*64]; // [n=g*32+o][k] hi
__device__ __align__(16) __nv_bfloat16 g_Wtl[128*64]; // lo

// ---------------- helpers -----------------------------------------------------
#define SWZ(x)   ((x) ^ (((x) >> 3) & 0x70))   // 128B rows

__device__ __forceinline__ uint32_t smem_u32(const void* p) {
  uint32_t a;
  asm("{ .reg .u64 t; cvta.to.shared.u64 t, %1; cvt.u32.u64 %0, t; }"
      : "=r"(a) : "l"(p));
  return a;
}

__device__ __forceinline__ void cpa16(uint32_t dst, const void* src) {
  asm volatile("cp.async.cg.shared.global [%0], [%1], 16;"
               :: "r"(dst), "l"(src) : "memory");
}
__device__ __forceinline__ void cpa16_ca(uint32_t dst, const void* src) {
  asm volatile("cp.async.ca.shared.global [%0], [%1], 16;"
               :: "r"(dst), "l"(src) : "memory");
}
#define CP_COMMIT() asm volatile("cp.async.commit_group;" ::: "memory")
#define CP_WAIT(n)  asm volatile("cp.async.wait_group %0;" :: "n"(n) : "memory")

__device__ __forceinline__ void ldm4(uint32_t* r, uint32_t addr) {
  asm volatile("ldmatrix.sync.aligned.m8n8.x4.shared.b16 {%0,%1,%2,%3}, [%4];"
               : "=r"(r[0]), "=r"(r[1]), "=r"(r[2]), "=r"(r[3]) : "r"(addr));
}

__device__ __forceinline__ void mma16816(float* c, const uint32_t* a,
                                         const uint32_t* b) {
  asm volatile(
      "mma.sync.aligned.m16n8k16.row.col.f32.bf16.bf16.f32 "
      "{%0,%1,%2,%3},{%4,%5,%6,%7},{%8,%9},{%0,%1,%2,%3};"
      : "+f"(c[0]), "+f"(c[1]), "+f"(c[2]), "+f"(c[3])
      : "r"(a[0]), "r"(a[1]), "r"(a[2]), "r"(a[3]), "r"(b[0]), "r"(b[1]));
}

__device__ __forceinline__ void mma16816h(float* c, const uint32_t* a,
                                          const uint32_t* b) {
  asm volatile(
      "mma.sync.aligned.m16n8k16.row.col.f32.f16.f16.f32 "
      "{%0,%1,%2,%3},{%4,%5,%6,%7},{%8,%9},{%0,%1,%2,%3};"
      : "+f"(c[0]), "+f"(c[1]), "+f"(c[2]), "+f"(c[3])
      : "r"(a[0]), "r"(a[1]), "r"(a[2]), "r"(a[3]), "r"(b[0]), "r"(b[1]));
}

__device__ __forceinline__ uint32_t pack2(__nv_bfloat16 a, __nv_bfloat16 b) {
  __nv_bfloat162 t(a, b);
  return *reinterpret_cast<uint32_t*>(&t);
}
__device__ __forceinline__ uint32_t pack2h(__half a, __half b) {
  __half2 t(a, b);
  return *reinterpret_cast<uint32_t*>(&t);
}

// ================= bf16 3-term GEMM (Chebyshev only) =========================
// 64x128 tile, KC=64, 3-stage. C = alpha*A@B~^T + beta*Cin.
__device__ __forceinline__ void load_chunk_b(
    uint32_t sb, int s, int kc, int tid, int brow, int bcol,
    const __nv_bfloat16* a0, const __nv_bfloat16* a1,
    const __nv_bfloat16* b0, const __nv_bfloat16* b1)
{
  constexpr int ASTAGE = 64 * 128;
  constexpr int BSTAGE = 128 * 128;
  constexpr int STAGE  = 2 * ASTAGE + 2 * BSTAGE;   // 48 KB
#pragma unroll
  for (int i = 0; i < 12; i++) {
    int idx = tid + i * 256;
    int cc = idx & 7;
    int rowIdx = idx >> 3;
    const __nv_bfloat16* src;
    uint32_t dstbase;
    if (rowIdx < 128) {
      int mat = rowIdx >> 6;
      int row = rowIdx & 63;
      src = (mat ? a1 : a0) + (ll)(brow + row) * ND + kc * 64 + cc * 8;
      dstbase = mat * ASTAGE + SWZ(row * 128 + cc * 16);
    } else {
      int rr = rowIdx - 128;
      int mat = rr >> 7;
      int row = rr & 127;
      src = (mat ? b1 : b0) + (ll)(bcol + row) * ND + kc * 64 + cc * 8;
      dstbase = 2 * ASTAGE + mat * BSTAGE + SWZ(row * 128 + cc * 16);
    }
    cpa16(sb + s * STAGE + dstbase, src);
  }
}

__global__ __launch_bounds__(256, 1) void tc_gemm_cheb(
    const __nv_bfloat16* __restrict__ Ah, const __nv_bfloat16* __restrict__ Al,
    const __nv_bfloat16* __restrict__ Bh, const __nv_bfloat16* __restrict__ Bl,
    const float* __restrict__ Cin, float* __restrict__ Cout,
    __nv_bfloat16* __restrict__ Couth, __nv_bfloat16* __restrict__ Coutl,
    __half* __restrict__ Coutf16,
    ll sAz, ll sBz, ll sCinz, ll sCz, float alpha, float beta, int cinmode)
{
  extern __shared__ char dsm[];
  constexpr int ASTAGE = 64 * 128;
  constexpr int BSTAGE = 128 * 128;
  constexpr int STAGE  = 2 * ASTAGE + 2 * BSTAGE;

  int z = blockIdx.z;
  const __nv_bfloat16* ah = Ah + sAz * z;
  const __nv_bfloat16* al = Al + sAz * z;
  const __nv_bfloat16* bh = Bh + sBz * z;
  const __nv_bfloat16* bl = Bl + sBz * z;
  const int brow = blockIdx.y * 64;
  const int bcol = blockIdx.x * 128;

  int tid = threadIdx.x;
  int lane = tid & 31;
  int wid = tid >> 5;
  int wrow = (wid & 1) * 32;
  int wcol = (wid >> 1) * 32;

  uint32_t raw = smem_u32(dsm);
  uint32_t sb = (raw + 1023) & ~1023u;

  float acc[2][4][4];
#pragma unroll
  for (int mi = 0; mi < 2; mi++)
#pragma unroll
    for (int ni = 0; ni < 4; ni++)
#pragma unroll
      for (int e = 0; e < 4; e++) acc[mi][ni][e] = 0.0f;

  int a_r  = (lane & 7) + ((lane >> 3) & 1) * 8;
  int a_k8 = ((lane >> 4) & 1) * 8;
  int b_r  = (lane & 7) + ((lane >> 4) & 1) * 8;
  int b_k8 = ((lane >> 3) & 1) * 8;

  load_chunk_b(sb, 0, 0, tid, brow, bcol, ah, al, bh, bl); CP_COMMIT();
  load_chunk_b(sb, 1, 1, tid, brow, bcol, ah, al, bh, bl); CP_COMMIT();

  for (int kc = 0; kc < 12; kc++) {
    if (kc < 11) { CP_WAIT(1); } else { CP_WAIT(0); }
    __syncthreads();

    uint32_t st  = sb + (kc % 3) * STAGE;
    uint32_t tAh = st;
    uint32_t tAl = st + ASTAGE;
    uint32_t tBh = st + 2 * ASTAGE;
    uint32_t tBl = tBh + BSTAGE;

#pragma unroll
    for (int s = 0; s < 4; s++) {
      uint32_t fah[2][4], fal[2][4];
#pragma unroll
      for (int mi = 0; mi < 2; mi++) {
        int r = wrow + mi * 16 + a_r;
        uint32_t off = SWZ(r * 128 + (s * 16 + a_k8) * 2);
        ldm4(fah[mi], tAh + off);
        ldm4(fal[mi], tAl + off);
      }
      uint32_t fbh[4][2], fbl[4][2];
#pragma unroll
      for (int nj2 = 0; nj2 < 2; nj2++) {
        int r = wcol + nj2 * 16 + b_r;
        uint32_t off = SWZ(r * 128 + (s * 16 + b_k8) * 2);
        uint32_t t4[4];
        ldm4(t4, tBh + off);
        fbh[nj2 * 2][0] = t4[0]; fbh[nj2 * 2][1] = t4[1];
        fbh[nj2 * 2 + 1][0] = t4[2]; fbh[nj2 * 2 + 1][1] = t4[3];
        ldm4(t4, tBl + off);
        fbl[nj2 * 2][0] = t4[0]; fbl[nj2 * 2][1] = t4[1];
        fbl[nj2 * 2 + 1][0] = t4[2]; fbl[nj2 * 2 + 1][1] = t4[3];
      }
#pragma unroll
      for (int mi = 0; mi < 2; mi++)
#pragma unroll
        for (int nl = 0; nl < 4; nl++)
          mma16816(acc[mi][nl], fah[mi], fbh[nl]);
#pragma unroll
      for (int mi = 0; mi < 2; mi++)
#pragma unroll
        for (int nl = 0; nl < 4; nl++)
          mma16816(acc[mi][nl], fah[mi], fbl[nl]);
#pragma unroll
      for (int mi = 0; mi < 2; mi++)
#pragma unroll
        for (int nl = 0; nl < 4; nl++)
          mma16816(acc[mi][nl], fal[mi], fbh[nl]);
    }

    if (kc + 2 < 12) {
      load_chunk_b(sb, (kc + 2) % 3, kc + 2, tid, brow, bcol, ah, al, bh, bl);
      CP_COMMIT();
    }
  }

  const float* cinp = (cinmode == 2) ? (Cin + sCinz * z) : (const float*)0;
  float* co = Cout + sCz * z;
  __nv_bfloat16* coh = Couth + sCz * z;
  __nv_bfloat16* col = Coutl + sCz * z;
  __half* cof = Coutf16 + sCz * z;
  int qr = lane >> 2, qc = lane & 3;

#pragma unroll
  for (int mi = 0; mi < 2; mi++) {
#pragma unroll
    for (int ni = 0; ni < 4; ni++) {
      int gr0 = brow + wrow + mi * 16 + qr;
      int gc  = bcol + wcol + ni * 8 + qc * 2;
      float2 v0, v1;
      v0.x = alpha * acc[mi][ni][0];
      v0.y = alpha * acc[mi][ni][1];
      v1.x = alpha * acc[mi][ni][2];
      v1.y = alpha * acc[mi][ni][3];
      if (cinmode == 2) {
        float2 c0 = *(const float2*)&cinp[(ll)gr0 * ND + gc];
        float2 c1 = *(const float2*)&cinp[(ll)(gr0 + 8) * ND + gc];
        v0.x += beta * c0.x; v0.y += beta * c0.y;
        v1.x += beta * c1.x; v1.y += beta * c1.y;
      } else if (cinmode == 1) {
        if (gr0 == gc)         v0.x += beta;
        if (gr0 == gc + 1)     v0.y += beta;
        if (gr0 + 8 == gc)     v1.x += beta;
        if (gr0 + 8 == gc + 1) v1.y += beta;
      }
      *(float2*)&co[(ll)gr0 * ND + gc]       = v0;
      *(float2*)&co[(ll)(gr0 + 8) * ND + gc] = v1;
      __nv_bfloat16 h0 = __float2bfloat16(v0.x);
      __nv_bfloat16 h1 = __float2bfloat16(v0.y);
      __nv_bfloat16 h2 = __float2bfloat16(v1.x);
      __nv_bfloat16 h3 = __float2bfloat16(v1.y);
      *(uint32_t*)&coh[(ll)gr0 * ND + gc]       = pack2(h0, h1);
      *(uint32_t*)&coh[(ll)(gr0 + 8) * ND + gc] = pack2(h2, h3);
      *(uint32_t*)&col[(ll)gr0 * ND + gc] =
          pack2(__float2bfloat16(v0.x - __bfloat162float(h0)),
                __float2bfloat16(v0.y - __bfloat162float(h1)));
      *(uint32_t*)&col[(ll)(gr0 + 8) * ND + gc] =
          pack2(__float2bfloat16(v1.x - __bfloat162float(h2)),
                __float2bfloat16(v1.y - __bfloat162float(h3)));
      *(uint32_t*)&cof[(ll)gr0 * ND + gc] =
          pack2h(__float2half(v0.x), __float2half(v0.y));
      *(uint32_t*)&cof[(ll)(gr0 + 8) * ND + gc] =
          pack2h(__float2half(v1.x), __float2half(v1.y));
    }
  }
}

// ================= fp16 single-term GEMM (Y and bf) ==========================
// TMx128 tile, KC=64, NS=3. C = A@B~^T (fp16 in, fp32 accum).
template<int TM>
__device__ __forceinline__ void load_chunk_h(
    uint32_t sb, int s, int kc, int tid, int brow, int bcol,
    const __half* a, const __half* b)
{
  constexpr int ASTAGE = TM * 128;
  constexpr int STAGE  = ASTAGE + 128 * 128;
  constexpr int ITER   = (TM + 128) * 8 / 256;
#pragma unroll
  for (int i = 0; i < ITER; i++) {
    int idx = tid + i * 256;
    int cc = idx & 7;
    int rowIdx = idx >> 3;
    const __half* src;
    uint32_t dstbase;
    if (rowIdx < TM) {
      src = a + (ll)(brow + rowIdx) * ND + kc * 64 + cc * 8;
      dstbase = SWZ(rowIdx * 128 + cc * 16);
    } else {
      int row = rowIdx - TM;
      src = b + (ll)(bcol + row) * ND + kc * 64 + cc * 8;
      dstbase = ASTAGE + SWZ(row * 128 + cc * 16);
    }
    cpa16(sb + s * STAGE + dstbase, src);
  }
}

template<int TM>
__global__ __launch_bounds__(256, 2) void tc_gemm16(
    const __half* __restrict__ A, const __half* __restrict__ B,
    float* __restrict__ Cout, __half* __restrict__ Coutf16,
    ll sAz, ll sAdiv, int adiv,
    ll sBz, ll sBmod, int bmod, ll sCz)
{
  extern __shared__ char dsm[];
  constexpr int ASTAGE = TM * 128;
  constexpr int STAGE  = ASTAGE + 128 * 128;
  constexpr int NI = (TM == 128) ? 8 : 4;
  constexpr int NPAIR = NI / 4;

  int z = blockIdx.z;
  const __half* a = A + sAz * z + sAdiv * (z / adiv);
  const __half* b = B + sBz * z + sBmod * (z % bmod);
  const int brow = blockIdx.y * TM;
  const int bcol = blockIdx.x * 128;

  int tid = threadIdx.x;
  int lane = tid & 31;
  int wid = tid >> 5;
  int wrow, wcol;
  if (TM == 128) { wrow = (wid & 3) * 32; wcol = (wid >> 2) * 64; }
  else           { wrow = (wid & 1) * 32; wcol = (wid >> 1) * 32; }

  uint32_t raw = smem_u32(dsm);
  uint32_t sb = (raw + 1023) & ~1023u;

  float acc[2][NI][4];
#pragma unroll
  for (int mi = 0; mi < 2; mi++)
#pragma unroll
    for (int ni = 0; ni < NI; ni++)
#pragma unroll
      for (int e = 0; e < 4; e++) acc[mi][ni][e] = 0.0f;

  int a_r  = (lane & 7) + ((lane >> 3) & 1) * 8;
  int a_k8 = ((lane >> 4) & 1) * 8;
  int b_r  = (lane & 7) + ((lane >> 4) & 1) * 8;
  int b_k8 = ((lane >> 3) & 1) * 8;

  load_chunk_h<TM>(sb, 0, 0, tid, brow, bcol, a, b); CP_COMMIT();
  load_chunk_h<TM>(sb, 1, 1, tid, brow, bcol, a, b); CP_COMMIT();

  for (int kc = 0; kc < 12; kc++) {
    if (kc < 11) { CP_WAIT(1); } else { CP_WAIT(0); }
    __syncthreads();

    uint32_t st = sb + (kc % 3) * STAGE;
    uint32_t tA = st;
    uint32_t tB = st + ASTAGE;

#pragma unroll
    for (int s = 0; s < 4; s++) {
      uint32_t fa[2][4];
#pragma unroll
      for (int mi = 0; mi < 2; mi++) {
        int r = wrow + mi * 16 + a_r;
        ldm4(fa[mi], tA + SWZ(r * 128 + (s * 16 + a_k8) * 2));
      }
#pragma unroll
      for (int p = 0; p < NPAIR; p++) {
        uint32_t fb[4][2];
#pragma unroll
        for (int nj2 = 0; nj2 < 2; nj2++) {
          int r = wcol + (p * 2 + nj2) * 16 + b_r;
          uint32_t t4[4];
          ldm4(t4, tB + SWZ(r * 128 + (s * 16 + b_k8) * 2));
          fb[nj2 * 2][0] = t4[0]; fb[nj2 * 2][1] = t4[1];
          fb[nj2 * 2 + 1][0] = t4[2]; fb[nj2 * 2 + 1][1] = t4[3];
        }
#pragma unroll
        for (int mi = 0; mi < 2; mi++)
#pragma unroll
          for (int nl = 0; nl < 4; nl++)
            mma16816h(acc[mi][p * 4 + nl], fa[mi], fb[nl]);
      }
    }

    if (kc + 2 < 12) {
      load_chunk_h<TM>(sb, (kc + 2) % 3, kc + 2, tid, brow, bcol, a, b);
      CP_COMMIT();
    }
  }

  float* co = Cout ? (Cout + sCz * z) : (float*)0;
  __half* cof = Coutf16 ? (Coutf16 + sCz * z) : (__half*)0;
  int qr = lane >> 2, qc = lane & 3;

#pragma unroll
  for (int mi = 0; mi < 2; mi++) {
#pragma unroll
    for (int ni = 0; ni < NI; ni++) {
      int gr0 = brow + wrow + mi * 16 + qr;
      int gc  = bcol + wcol + ni * 8 + qc * 2;
      float2 v0, v1;
      v0.x = acc[mi][ni][0]; v0.y = acc[mi][ni][1];
      v1.x = acc[mi][ni][2]; v1.y = acc[mi][ni][3];
      if (co) {
        *(float2*)&co[(ll)gr0 * ND + gc]       = v0;
        *(float2*)&co[(ll)(gr0 + 8) * ND + gc] = v1;
      }
      if (cof) {
        *(uint32_t*)&cof[(ll)gr0 * ND + gc] =
            pack2h(__float2half(v0.x), __float2half(v0.y));
        *(uint32_t*)&cof[(ll)(gr0 + 8) * ND + gc] =
            pack2h(__float2half(v1.x), __float2half(v1.y));
      }
    }
  }
}

// ---------------- merged setup (single launch) -------------------------------
// z=0: L_row -> Tf+S + Tsh/Tsl+S + Tf16+S    z=1: L_col -> +6S
// z=2: x -> xcur fp32 + Y16 slot0 fp16       z=3: W/U split (32 blocks)
// z=4: x -> xT16 fp16 (transpose)
__global__ __launch_bounds__(256) void setup_kernel(
    const float* __restrict__ L_row, const float* __restrict__ L_col,
    float* __restrict__ Tf, __nv_bfloat16* __restrict__ Tsh,
    __nv_bfloat16* __restrict__ Tsl, __half* __restrict__ Tf16,
    const float* __restrict__ x, float* __restrict__ xcur,
    __half* __restrict__ Y16, __half* __restrict__ xT16,
    const float* __restrict__ Wf, const float* __restrict__ Uf,
    const float* __restrict__ Wi, const float* __restrict__ Ui,
    const float* __restrict__ Wo, const float* __restrict__ Uo,
    const float* __restrict__ Wc, const float* __restrict__ Uc,
    __nv_bfloat16* __restrict__ Wth, __nv_bfloat16* __restrict__ Wtl)
{
  __shared__ float ts[32][33];
  int z = blockIdx.z;
  int t = threadIdx.x;

  if (z == 3) {
    if (blockIdx.x >= 32) return;
    const float* Ws[4] = {Wf, Wi, Wo, Wc};
    const float* Us[4] = {Uf, Ui, Uo, Uc};
    int idx = blockIdx.x * 256 + t;
    int n = idx >> 6, k = idx & 63;
    int g = n >> 5, o = n & 31;
    float v = (k < 32) ? Ws[g][k * 32 + o] : Us[g][(k - 32) * 32 + o];
    __nv_bfloat16 vh = __float2bfloat16(v);
    Wth[idx] = vh;
    Wtl[idx] = __float2bfloat16(v - __bfloat162float(vh));
    return;
  }
  if (z == 4) {                        // transpose fp16 split of x
    int bx = (blockIdx.x % 24) * 32, by = (blockIdx.x / 24) * 32;
    int tx = t & 31, ty = t >> 5;
#pragma unroll
    for (int i = 0; i < 4; i++)
      ts[ty + 8 * i][tx] = x[(ll)(by + ty + 8 * i) * ND + bx + tx];
    __syncthreads();
#pragma unroll
    for (int i = 0; i < 4; i++)
      xT16[(ll)(bx + ty + 8 * i) * ND + by + tx] = __float2half(ts[tx][ty + 8 * i]);
    return;
  }
  if (z == 2) {
    int idx = blockIdx.x * 256 + t;
    float4 v = *(const float4*)(x + (ll)idx * 4);
    *(float4*)(xcur + (ll)idx * 4) = v;
    uint2 uf;
    uf.x = pack2h(__float2half(v.x), __float2half(v.y));
    uf.y = pack2h(__float2half(v.z), __float2half(v.w));
    *(uint2*)(Y16 + (ll)idx * 4) = uf;
    return;
  }

  const float* src = (z == 0) ? L_row : L_col;
  ll off = (z == 0) ? (ll)SZ : (ll)6 * SZ;
  int idx = blockIdx.x * 256 + t;
  float4 v = *(const float4*)(src + (ll)idx * 4);
  *(float4*)(Tf + off + (ll)idx * 4) = v;
  float a[4] = {v.x, v.y, v.z, v.w};
  __nv_bfloat16 h[4];
  uint2 uh, ul, uf;
#pragma unroll
  for (int e = 0; e < 4; e++) h[e] = __float2bfloat16(a[e]);
  uh.x = pack2(h[0], h[1]); uh.y = pack2(h[2], h[3]);
  ul.x = pack2(__float2bfloat16(a[0] - __bfloat162float(h[0])),
               __float2bfloat16(a[1] - __bfloat162float(h[1])));
  ul.y = pack2(__float2bfloat16(a[2] - __bfloat162float(h[2])),
               __float2bfloat16(a[3] - __bfloat162float(h[3])));
  uf.x = pack2h(__float2half(a[0]), __float2half(a[1]));
  uf.y = pack2h(__float2half(a[2]), __float2half(a[3]));
  *(uint2*)(Tsh + off + (ll)idx * 4) = uh;
  *(uint2*)(Tsl + off + (ll)idx * 4) = ul;
  *(uint2*)(Tf16 + off + (ll)idx * 4) = uf;
}

// ---------------- fused_rnn v6 (fp16 x outputs) -------------------------------
__device__ __forceinline__ float sigf(float v) {
  return __fdividef(1.0f, 1.0f + __expf(-v));
}

__global__ __launch_bounds__(256, 2) void fused_rnn(
    const float* __restrict__ Yf_g, const float* __restrict__ bff_g,
    const float* __restrict__ theta, const float* __restrict__ bias,
    const __nv_bfloat16* __restrict__ Wth, const __nv_bfloat16* __restrict__ Wtl,
    const float* __restrict__ bf_, const float* __restrict__ bi_,
    const float* __restrict__ bo_, const float* __restrict__ bc_,
    const float* __restrict__ Wout, const float* __restrict__ bout,
    float* c, __nv_bfloat16* hh_g, __nv_bfloat16* hl_g, float* x,
    __half* __restrict__ xf16, __half* __restrict__ xT16,
    int first, int last)
{
  extern __shared__ char dsm[];
  uint32_t raw = smem_u32(dsm);
  uint32_t sb = (raw + 1023) & ~1023u;
  char* base = dsm + (sb - raw);

  float* th  = (float*)(base + 65536);
  float* bs  = (float*)(base + 65536 + 3200);
  float* swo = (float*)(base + 65536 + 3328);
  float* sbg = (float*)(base + 65536 + 3456);

  int t = threadIdx.x;
  int lane = t & 31;
  int w = t >> 5;
  size_t bpt = (size_t)blockIdx.x * 128;

  // ---- issue cp.async: W tiles (.ca) + h rows --------------------------------
#pragma unroll
  for (int i = 0; i < 8; i++) {
    int idx = t + i * 256;
    int mat = idx >> 10;
    int rr  = (idx >> 3) & 127;
    int c4  = idx & 7;
    const __nv_bfloat16* src = (mat ? Wtl : Wth) + rr * 64 + c4 * 8;
    cpa16_ca(sb + 32768 + mat * 16384 + SWZ(rr * 128 + c4 * 16), src);
  }
  if (!first) {
#pragma unroll
    for (int i = 0; i < 8; i++) {
      int idx = t + i * 256;
      int mat = idx >> 10;
      int rr  = (idx >> 2) & 127;
      int c4h = (idx & 3) + 4;
      const __nv_bfloat16* src =
          (mat ? hl_g : hh_g) + (bpt + rr) * 32 + (c4h - 4) * 8;
      cpa16(sb + mat * 16384 + SWZ(rr * 128 + c4h * 16), src);
    }
  } else {
    uint4 z4 = make_uint4(0, 0, 0, 0);
#pragma unroll
    for (int i = 0; i < 8; i++) {
      int idx = t + i * 256;
      int mat = idx >> 10;
      int rr  = (idx >> 2) & 127;
      int c4h = (idx & 3) + 4;
      *(uint4*)(base + mat * 16384 + SWZ(rr * 128 + c4h * 16)) = z4;
    }
  }
  CP_COMMIT();

  // ---- prefetch 25 conv-source values (fp32; before any sync) ----------------
  int r   = t & 127;
  int ohp = (t >> 7) * 16;
  size_t rg = bpt + r;
  float v[25];
  v[0] = __ldg(x + rg);
#pragma unroll
  for (int i = 1; i < 5; i++)
    v[i * 5] = __ldg(Yf_g + (ll)(i - 1) * SZ + rg);
#pragma unroll
  for (int i = 0; i < 5; i++)
#pragma unroll
    for (int j = 1; j < 5; j++)
      v[i * 5 + j] = __ldg(bff_g + (ll)(i * 4 + j - 1) * SZ + rg);

  // ---- scalars ---------------------------------------------------------------
  for (int i = t; i < 800; i += 256) th[i] = theta[i];
  if (t < 32) { bs[t] = bias[t]; swo[t] = Wout[t]; }
  if (t < 128) { const float* bx[4] = {bf_, bi_, bo_, bc_}; sbg[t] = bx[t >> 5][t & 31]; }
  __syncthreads();

  // ---- combine -> A cols 0..31 (xc split bf16) -------------------------------
  {
    float out[16];
#pragma unroll
    for (int o = 0; o < 16; o++) out[o] = bs[ohp + o];
#pragma unroll
    for (int ij = 0; ij < 25; ij++) {
      const float* tw = &th[ij * 32 + ohp];
#pragma unroll
      for (int o = 0; o < 16; o++) out[o] += v[ij] * tw[o];
    }
#pragma unroll
    for (int i = 0; i < 8; i++) {
      float a0 = out[2 * i], a1 = out[2 * i + 1];
      __nv_bfloat16 h0 = __float2bfloat16(a0);
      __nv_bfloat16 h1 = __float2bfloat16(a1);
      uint32_t byte = r * 128 + (ohp + 2 * i) * 2;
      *(uint32_t*)(base + SWZ(byte)) = pack2(h0, h1);
      *(uint32_t*)(base + 16384 + SWZ(byte)) =
          pack2(__float2bfloat16(a0 - __bfloat162float(h0)),
                __float2bfloat16(a1 - __bfloat162float(h1)));
    }
  }
  CP_WAIT(0);
  __syncthreads();

  // ---- HMMA: PRE[128 pt x 128 n] = A @ W^T (3-term split) --------------------
  int a_r  = (lane & 7) + ((lane >> 3) & 1) * 8;
  int a_k8 = ((lane >> 4) & 1) * 8;
  int b_r  = (lane & 7) + ((lane >> 4) & 1) * 8;
  int b_k8 = ((lane >> 3) & 1) * 8;

  float acc[16][4];
#pragma unroll
  for (int nt = 0; nt < 16; nt++)
#pragma unroll
    for (int e = 0; e < 4; e++) acc[nt][e] = 0.0f;

#pragma unroll
  for (int ks = 0; ks < 4; ks++) {
    uint32_t abyte = SWZ((w * 16 + a_r) * 128 + (ks * 16 + a_k8) * 2);
    uint32_t ah4[4], al4[4];
    ldm4(ah4, sb + abyte);
    ldm4(al4, sb + 16384 + abyte);
#pragma unroll
    for (int np = 0; np < 8; np++) {
      uint32_t bbyte = SWZ((np * 16 + b_r) * 128 + (ks * 16 + b_k8) * 2);
      uint32_t bh4[4], bl4[4];
      ldm4(bh4, sb + 32768 + bbyte);
      ldm4(bl4, sb + 49152 + bbyte);
      mma16816(acc[2 * np],     ah4, bh4);
      mma16816(acc[2 * np + 1], ah4, bh4 + 2);
      mma16816(acc[2 * np],     ah4, bl4);
      mma16816(acc[2 * np + 1], ah4, bl4 + 2);
      mma16816(acc[2 * np],     al4, bh4);
      mma16816(acc[2 * np + 1], al4, bh4 + 2);
    }
  }

  // ---- in-register gates + c/h update + dx partials --------------------------
  int qr = lane >> 2, qc = lane & 3;
  size_t p0 = bpt + w * 16 + qr;
  float pd[2] = {0.0f, 0.0f};

#pragma unroll
  for (int m = 0; m < 4; m++) {
#pragma unroll
    for (int rh = 0; rh < 2; rh++) {
      size_t pt = p0 + 8 * rh;
      int ob = 8 * m + 2 * qc;
      float2 cold = make_float2(0.0f, 0.0f);
      if (!first) cold = *(const float2*)&c[pt * 32 + ob];
      float cn[2], hn[2];
#pragma unroll
      for (int p = 0; p < 2; p++) {
        int o = ob + p;
        int e = p + 2 * rh;
        float zi = acc[4 + m][e]  + sbg[32 + o];
        float zc = acc[12 + m][e] + sbg[96 + o];
        float cnew = sigf(zi) * sigf(zc);
        if (!first) {
          float zf = acc[m][e] + sbg[o];
          cnew += sigf(zf) * (p ? cold.y : cold.x);
        }
        cn[p] = cnew;
        pd[rh] += cnew * swo[o];
        if (!last) {
          float zo = acc[8 + m][e] + sbg[64 + o];
          hn[p] = sigf(zo) * sigf(cnew);
        }
      }
      if (!last) {
        *(float2*)&c[pt * 32 + ob] = make_float2(cn[0], cn[1]);
        __nv_bfloat16 h0 = __float2bfloat16(hn[0]);
        __nv_bfloat16 h1 = __float2bfloat16(hn[1]);
        *(uint32_t*)&hh_g[pt * 32 + ob] = pack2(h0, h1);
        *(uint32_t*)&hl_g[pt * 32 + ob] =
            pack2(__float2bfloat16(hn[0] - __bfloat162float(h0)),
                  __float2bfloat16(hn[1] - __bfloat162float(h1)));
      }
    }
  }

#pragma unroll
  for (int rh = 0; rh < 2; rh++) {
    pd[rh] += __shfl_xor_sync(0xFFFFFFFF, pd[rh], 1);
    pd[rh] += __shfl_xor_sync(0xFFFFFFFF, pd[rh], 2);
  }
  if (qc == 0) {
    float b0 = __ldg(bout);
#pragma unroll
    for (int rh = 0; rh < 2; rh++) {
      size_t gi = p0 + 8 * rh;
      float xn = x[gi] + tanhf(pd[rh] + b0);
      x[gi] = xn;
      if (!last) {
        __half xh = __float2half(xn);
        xf16[gi] = xh;
        int row = (int)(gi / ND);
        int col = (int)(gi - (size_t)row * ND);
        xT16[(ll)col * ND + row] = xh;
      }
    }
  }
}

// ---------------- orchestration ----------------------------------------------
extern "C" void kernel_launch(void* const* d_in, const int* in_sizes, int n_in,
                              void* d_out, int out_size)
{
  const float* x     = (const float*)d_in[0];
  const float* L_row = (const float*)d_in[1];
  const float* L_col = (const float*)d_in[2];
  const float* theta = (const float*)d_in[3];
  const float* bias  = (const float*)d_in[4];
  const float* W_f = (const float*)d_in[5];
  const float* U_f = (const float*)d_in[6];
  const float* b_f = (const float*)d_in[7];
  const float* W_i = (const float*)d_in[8];
  const float* U_i = (const float*)d_in[9];
  const float* b_i = (const float*)d_in[10];
  const float* W_o = (const float*)d_in[11];
  const float* U_o = (const float*)d_in[12];
  const float* b_o = (const float*)d_in[13];
  const float* W_c = (const float*)d_in[14];
  const float* U_c = (const float*)d_in[15];
  const float* b_c = (const float*)d_in[16];
  const float* W_out = (const float*)d_in[17];
  const float* b_out = (const float*)d_in[18];
  // d_in[19] = nb_iterations_rnn = 3 (fixed by setup)

  float* xcur = (float*)d_out;

  float *Tf, *Yf, *bff, *c;
  __nv_bfloat16 *Tsh, *Tsl, *hh, *hl, *Wth, *Wtl;
  __half *Tf16, *xT16, *Y16;
  cudaGetSymbolAddress((void**)&Tf,   g_Tf);
  cudaGetSymbolAddress((void**)&Tsh,  g_Tsh);
  cudaGetSymbolAddress((void**)&Tsl,  g_Tsl);
  cudaGetSymbolAddress((void**)&Tf16, g_Tf16);
  cudaGetSymbolAddress((void**)&xT16, g_xT16);
  cudaGetSymbolAddress((void**)&Yf,   g_Yf);
  cudaGetSymbolAddress((void**)&Y16,  g_Y16);
  cudaGetSymbolAddress((void**)&bff,  g_bff);
  cudaGetSymbolAddress((void**)&hh,   g_hh);
  cudaGetSymbolAddress((void**)&hl,   g_hl);
  cudaGetSymbolAddress((void**)&c,    g_c);
  cudaGetSymbolAddress((void**)&Wth,  g_Wth);
  cudaGetSymbolAddress((void**)&Wtl,  g_Wtl);

  const ll S = SZ;
  const int DSM_CHEB = 1024 + 3 * 49152;               // bf16 3-term, 48KB stages
  const int DSM_Y    = 1024 + 3 * ((64 + 128) * 128);  // fp16, 24KB stages
  const int DSM_BF   = 1024 + 3 * ((128 + 128) * 128); // fp16, 32KB stages
  const int FSM      = 1024 + 65536 + 3968;
  cudaFuncSetAttribute((const void*)tc_gemm_cheb, cudaFuncAttributeMaxDynamicSharedMemorySize, DSM_CHEB);
  cudaFuncSetAttribute((const void*)tc_gemm16<64>,  cudaFuncAttributeMaxDynamicSharedMemorySize, DSM_Y);
  cudaFuncSetAttribute((const void*)tc_gemm16<128>, cudaFuncAttributeMaxDynamicSharedMemorySize, DSM_BF);
  cudaFuncSetAttribute((const void*)fused_rnn,      cudaFuncAttributeMaxDynamicSharedMemorySize, FSM);

  // launch 1: merged setup
  {
    dim3 g(SZ / 1024, 1, 5);
    setup_kernel<<<g, 256>>>(L_row, L_col, Tf, Tsh, Tsl, Tf16,
                             x, xcur, Y16, xT16,
                             W_f, U_f, W_i, U_i, W_o, U_o, W_c, U_c, Wth, Wtl);
  }

  // Chebyshev recursion (bf16 3-term; emits fp32 + bf16 split + fp16)
  for (int k = 2; k <= 4; k++) {
    dim3 g(6, 12, 2);
    int cinmode = (k == 2) ? 1 : 2;
    const float* cin = (k == 2) ? (const float*)0 : (Tf + (ll)(k - 2) * S);
    tc_gemm_cheb<<<g, 256, DSM_CHEB>>>(
        Tsh + S, Tsl + S,
        Tsh + (ll)(k - 1) * S, Tsl + (ll)(k - 1) * S,
        cin, Tf + (ll)k * S, Tsh + (ll)k * S, Tsl + (ll)k * S, Tf16 + (ll)k * S,
        5 * S, 5 * S, 5 * S, 5 * S, 2.0f, -1.0f, cinmode);
  }

  for (int it = 0; it < 3; it++) {
    // Y_{1+z} = Tr_{1+z} @ x   (fp16 single-term)
    {
      dim3 g(6, 12, 4);
      tc_gemm16<64><<<g, 256, DSM_Y>>>(
          Tf16 + S, xT16, Yf, Y16 + S,
          S, 0, 1,    0, 0, 1,    S);
    }
    // bf[z] = Y_{z/4} @ Tc_{1+z%4}   (fp16 single-term)
    {
      dim3 g(6, 6, 20);
      tc_gemm16<128><<<g, 256, DSM_BF>>>(
          Y16, Tf16 + 6 * S, bff, (__half*)0,
          0, S, 4,    0, S, 4,    S);
    }
    fused_rnn<<<SZ / 128, 256, FSM>>>(
        Yf, bff, theta, bias, Wth, Wtl,
        b_f, b_i, b_o, b_c, W_out, b_out,
        c, hh, hl, xcur, Y16, xT16,
        (it == 0) ? 1 : 0, (it == 2) ? 1 : 0);
  }
}

// round 13
// speedup vs baseline: 1.5849x; 1.1493x over previous
#include <cuda_runtime.h>
#include <cuda_bf16.h>
#include <cuda_fp16.h>
#include <cstdint>

#define ND 768
#define SZ (768*768)
#define MNTOT SZ
typedef long long ll;

// ---------------- scratch (device globals) ----------------------------------
__device__ float g_Tf[10*SZ];                         // fp32 T[side][k]
__device__ __align__(16) __nv_bfloat16 g_Tsh[10*SZ];  // bf16 hi (cheb)
__device__ __align__(16) __nv_bfloat16 g_Tsl[10*SZ];  // bf16 lo (cheb)
__device__ __align__(16) __half g_Tf16[10*SZ];        // fp16 T (Y/bf operands)
__device__ __align__(16) __half g_xT16[SZ];           // fp16 x^T
__device__ __align__(16) __half g_Y16[5*SZ];          // slot0 = x fp16; 1..4 = Y_i
__device__ __align__(16) __half g_bf16[20*SZ];        // bf products fp16
__device__ __align__(16) __half g_h16[32*SZ];         // h point-major [pt][32] fp16
__device__ float g_c[32*SZ];                          // c point-major [pt][32] fp32
__device__ __align__(16) __half g_Wt16[128*64];       // [n=g*32+o][k] fp16

// ---------------- helpers -----------------------------------------------------
#define SWZ(x)   ((x) ^ (((x) >> 3) & 0x70))   // 128B rows

__device__ __forceinline__ uint32_t smem_u32(const void* p) {
  uint32_t a;
  asm("{ .reg .u64 t; cvta.to.shared.u64 t, %1; cvt.u32.u64 %0, t; }"
      : "=r"(a) : "l"(p));
  return a;
}

__device__ __forceinline__ void cpa16(uint32_t dst, const void* src) {
  asm volatile("cp.async.cg.shared.global [%0], [%1], 16;"
               :: "r"(dst), "l"(src) : "memory");
}
__device__ __forceinline__ void cpa16_ca(uint32_t dst, const void* src) {
  asm volatile("cp.async.ca.shared.global [%0], [%1], 16;"
               :: "r"(dst), "l"(src) : "memory");
}
#define CP_COMMIT() asm volatile("cp.async.commit_group;" ::: "memory")
#define CP_WAIT(n)  asm volatile("cp.async.wait_group %0;" :: "n"(n) : "memory")

__device__ __forceinline__ void ldm4(uint32_t* r, uint32_t addr) {
  asm volatile("ldmatrix.sync.aligned.m8n8.x4.shared.b16 {%0,%1,%2,%3}, [%4];"
               : "=r"(r[0]), "=r"(r[1]), "=r"(r[2]), "=r"(r[3]) : "r"(addr));
}

__device__ __forceinline__ void mma16816(float* c, const uint32_t* a,
                                         const uint32_t* b) {
  asm volatile(
      "mma.sync.aligned.m16n8k16.row.col.f32.bf16.bf16.f32 "
      "{%0,%1,%2,%3},{%4,%5,%6,%7},{%8,%9},{%0,%1,%2,%3};"
      : "+f"(c[0]), "+f"(c[1]), "+f"(c[2]), "+f"(c[3])
      : "r"(a[0]), "r"(a[1]), "r"(a[2]), "r"(a[3]), "r"(b[0]), "r"(b[1]));
}

__device__ __forceinline__ void mma16816h(float* c, const uint32_t* a,
                                          const uint32_t* b) {
  asm volatile(
      "mma.sync.aligned.m16n8k16.row.col.f32.f16.f16.f32 "
      "{%0,%1,%2,%3},{%4,%5,%6,%7},{%8,%9},{%0,%1,%2,%3};"
      : "+f"(c[0]), "+f"(c[1]), "+f"(c[2]), "+f"(c[3])
      : "r"(a[0]), "r"(a[1]), "r"(a[2]), "r"(a[3]), "r"(b[0]), "r"(b[1]));
}

__device__ __forceinline__ uint32_t pack2(__nv_bfloat16 a, __nv_bfloat16 b) {
  __nv_bfloat162 t(a, b);
  return *reinterpret_cast<uint32_t*>(&t);
}
__device__ __forceinline__ uint32_t pack2h(__half a, __half b) {
  __half2 t(a, b);
  return *reinterpret_cast<uint32_t*>(&t);
}

// ================= bf16 3-term GEMM (Chebyshev only) =========================
__device__ __forceinline__ void load_chunk_b(
    uint32_t sb, int s, int kc, int tid, int brow, int bcol,
    const __nv_bfloat16* a0, const __nv_bfloat16* a1,
    const __nv_bfloat16* b0, const __nv_bfloat16* b1)
{
  constexpr int ASTAGE = 64 * 128;
  constexpr int BSTAGE = 128 * 128;
  constexpr int STAGE  = 2 * ASTAGE + 2 * BSTAGE;   // 48 KB
#pragma unroll
  for (int i = 0; i < 12; i++) {
    int idx = tid + i * 256;
    int cc = idx & 7;
    int rowIdx = idx >> 3;
    const __nv_bfloat16* src;
    uint32_t dstbase;
    if (rowIdx < 128) {
      int mat = rowIdx >> 6;
      int row = rowIdx & 63;
      src = (mat ? a1 : a0) + (ll)(brow + row) * ND + kc * 64 + cc * 8;
      dstbase = mat * ASTAGE + SWZ(row * 128 + cc * 16);
    } else {
      int rr = rowIdx - 128;
      int mat = rr >> 7;
      int row = rr & 127;
      src = (mat ? b1 : b0) + (ll)(bcol + row) * ND + kc * 64 + cc * 8;
      dstbase = 2 * ASTAGE + mat * BSTAGE + SWZ(row * 128 + cc * 16);
    }
    cpa16(sb + s * STAGE + dstbase, src);
  }
}

__global__ __launch_bounds__(256, 1) void tc_gemm_cheb(
    const __nv_bfloat16* __restrict__ Ah, const __nv_bfloat16* __restrict__ Al,
    const __nv_bfloat16* __restrict__ Bh, const __nv_bfloat16* __restrict__ Bl,
    const float* __restrict__ Cin, float* __restrict__ Cout,
    __nv_bfloat16* __restrict__ Couth, __nv_bfloat16* __restrict__ Coutl,
    __half* __restrict__ Coutf16,
    ll sAz, ll sBz, ll sCinz, ll sCz, float alpha, float beta, int cinmode)
{
  extern __shared__ char dsm[];
  constexpr int ASTAGE = 64 * 128;
  constexpr int BSTAGE = 128 * 128;
  constexpr int STAGE  = 2 * ASTAGE + 2 * BSTAGE;

  int z = blockIdx.z;
  const __nv_bfloat16* ah = Ah + sAz * z;
  const __nv_bfloat16* al = Al + sAz * z;
  const __nv_bfloat16* bh = Bh + sBz * z;
  const __nv_bfloat16* bl = Bl + sBz * z;
  const int brow = blockIdx.y * 64;
  const int bcol = blockIdx.x * 128;

  int tid = threadIdx.x;
  int lane = tid & 31;
  int wid = tid >> 5;
  int wrow = (wid & 1) * 32;
  int wcol = (wid >> 1) * 32;

  uint32_t raw = smem_u32(dsm);
  uint32_t sb = (raw + 1023) & ~1023u;

  float acc[2][4][4];
#pragma unroll
  for (int mi = 0; mi < 2; mi++)
#pragma unroll
    for (int ni = 0; ni < 4; ni++)
#pragma unroll
      for (int e = 0; e < 4; e++) acc[mi][ni][e] = 0.0f;

  int a_r  = (lane & 7) + ((lane >> 3) & 1) * 8;
  int a_k8 = ((lane >> 4) & 1) * 8;
  int b_r  = (lane & 7) + ((lane >> 4) & 1) * 8;
  int b_k8 = ((lane >> 3) & 1) * 8;

  load_chunk_b(sb, 0, 0, tid, brow, bcol, ah, al, bh, bl); CP_COMMIT();
  load_chunk_b(sb, 1, 1, tid, brow, bcol, ah, al, bh, bl); CP_COMMIT();

  for (int kc = 0; kc < 12; kc++) {
    if (kc < 11) { CP_WAIT(1); } else { CP_WAIT(0); }
    __syncthreads();

    uint32_t st  = sb + (kc % 3) * STAGE;
    uint32_t tAh = st;
    uint32_t tAl = st + ASTAGE;
    uint32_t tBh = st + 2 * ASTAGE;
    uint32_t tBl = tBh + BSTAGE;

#pragma unroll
    for (int s = 0; s < 4; s++) {
      uint32_t fah[2][4], fal[2][4];
#pragma unroll
      for (int mi = 0; mi < 2; mi++) {
        int r = wrow + mi * 16 + a_r;
        uint32_t off = SWZ(r * 128 + (s * 16 + a_k8) * 2);
        ldm4(fah[mi], tAh + off);
        ldm4(fal[mi], tAl + off);
      }
      uint32_t fbh[4][2], fbl[4][2];
#pragma unroll
      for (int nj2 = 0; nj2 < 2; nj2++) {
        int r = wcol + nj2 * 16 + b_r;
        uint32_t off = SWZ(r * 128 + (s * 16 + b_k8) * 2);
        uint32_t t4[4];
        ldm4(t4, tBh + off);
        fbh[nj2 * 2][0] = t4[0]; fbh[nj2 * 2][1] = t4[1];
        fbh[nj2 * 2 + 1][0] = t4[2]; fbh[nj2 * 2 + 1][1] = t4[3];
        ldm4(t4, tBl + off);
        fbl[nj2 * 2][0] = t4[0]; fbl[nj2 * 2][1] = t4[1];
        fbl[nj2 * 2 + 1][0] = t4[2]; fbl[nj2 * 2 + 1][1] = t4[3];
      }
#pragma unroll
      for (int mi = 0; mi < 2; mi++)
#pragma unroll
        for (int nl = 0; nl < 4; nl++)
          mma16816(acc[mi][nl], fah[mi], fbh[nl]);
#pragma unroll
      for (int mi = 0; mi < 2; mi++)
#pragma unroll
        for (int nl = 0; nl < 4; nl++)
          mma16816(acc[mi][nl], fah[mi], fbl[nl]);
#pragma unroll
      for (int mi = 0; mi < 2; mi++)
#pragma unroll
        for (int nl = 0; nl < 4; nl++)
          mma16816(acc[mi][nl], fal[mi], fbh[nl]);
    }

    if (kc + 2 < 12) {
      load_chunk_b(sb, (kc + 2) % 3, kc + 2, tid, brow, bcol, ah, al, bh, bl);
      CP_COMMIT();
    }
  }

  const float* cinp = (cinmode == 2) ? (Cin + sCinz * z) : (const float*)0;
  float* co = Cout + sCz * z;
  __nv_bfloat16* coh = Couth + sCz * z;
  __nv_bfloat16* col = Coutl + sCz * z;
  __half* cof = Coutf16 + sCz * z;
  int qr = lane >> 2, qc = lane & 3;

#pragma unroll
  for (int mi = 0; mi < 2; mi++) {
#pragma unroll
    for (int ni = 0; ni < 4; ni++) {
      int gr0 = brow + wrow + mi * 16 + qr;
      int gc  = bcol + wcol + ni * 8 + qc * 2;
      float2 v0, v1;
      v0.x = alpha * acc[mi][ni][0];
      v0.y = alpha * acc[mi][ni][1];
      v1.x = alpha * acc[mi][ni][2];
      v1.y = alpha * acc[mi][ni][3];
      if (cinmode == 2) {
        float2 c0 = *(const float2*)&cinp[(ll)gr0 * ND + gc];
        float2 c1 = *(const float2*)&cinp[(ll)(gr0 + 8) * ND + gc];
        v0.x += beta * c0.x; v0.y += beta * c0.y;
        v1.x += beta * c1.x; v1.y += beta * c1.y;
      } else if (cinmode == 1) {
        if (gr0 == gc)         v0.x += beta;
        if (gr0 == gc + 1)     v0.y += beta;
        if (gr0 + 8 == gc)     v1.x += beta;
        if (gr0 + 8 == gc + 1) v1.y += beta;
      }
      *(float2*)&co[(ll)gr0 * ND + gc]       = v0;
      *(float2*)&co[(ll)(gr0 + 8) * ND + gc] = v1;
      __nv_bfloat16 h0 = __float2bfloat16(v0.x);
      __nv_bfloat16 h1 = __float2bfloat16(v0.y);
      __nv_bfloat16 h2 = __float2bfloat16(v1.x);
      __nv_bfloat16 h3 = __float2bfloat16(v1.y);
      *(uint32_t*)&coh[(ll)gr0 * ND + gc]       = pack2(h0, h1);
      *(uint32_t*)&coh[(ll)(gr0 + 8) * ND + gc] = pack2(h2, h3);
      *(uint32_t*)&col[(ll)gr0 * ND + gc] =
          pack2(__float2bfloat16(v0.x - __bfloat162float(h0)),
                __float2bfloat16(v0.y - __bfloat162float(h1)));
      *(uint32_t*)&col[(ll)(gr0 + 8) * ND + gc] =
          pack2(__float2bfloat16(v1.x - __bfloat162float(h2)),
                __float2bfloat16(v1.y - __bfloat162float(h3)));
      *(uint32_t*)&cof[(ll)gr0 * ND + gc] =
          pack2h(__float2half(v0.x), __float2half(v0.y));
      *(uint32_t*)&cof[(ll)(gr0 + 8) * ND + gc] =
          pack2h(__float2half(v1.x), __float2half(v1.y));
    }
  }
}

// ================= fp16 single-term GEMM (Y and bf) ==========================
template<int TM>
__device__ __forceinline__ void load_chunk_h(
    uint32_t sb, int s, int kc, int tid, int brow, int bcol,
    const __half* a, const __half* b)
{
  constexpr int ASTAGE = TM * 128;
  constexpr int STAGE  = ASTAGE + 128 * 128;
  constexpr int ITER   = (TM + 128) * 8 / 256;
#pragma unroll
  for (int i = 0; i < ITER; i++) {
    int idx = tid + i * 256;
    int cc = idx & 7;
    int rowIdx = idx >> 3;
    const __half* src;
    uint32_t dstbase;
    if (rowIdx < TM) {
      src = a + (ll)(brow + rowIdx) * ND + kc * 64 + cc * 8;
      dstbase = SWZ(rowIdx * 128 + cc * 16);
    } else {
      int row = rowIdx - TM;
      src = b + (ll)(bcol + row) * ND + kc * 64 + cc * 8;
      dstbase = ASTAGE + SWZ(row * 128 + cc * 16);
    }
    cpa16(sb + s * STAGE + dstbase, src);
  }
}

template<int TM>
__global__ __launch_bounds__(256, 2) void tc_gemm16(
    const __half* __restrict__ A, const __half* __restrict__ B,
    __half* __restrict__ Coutf16,
    ll sAz, ll sAdiv, int adiv,
    ll sBz, ll sBmod, int bmod, ll sCz)
{
  extern __shared__ char dsm[];
  constexpr int ASTAGE = TM * 128;
  constexpr int STAGE  = ASTAGE + 128 * 128;
  constexpr int NI = (TM == 128) ? 8 : 4;
  constexpr int NPAIR = NI / 4;

  int z = blockIdx.z;
  const __half* a = A + sAz * z + sAdiv * (z / adiv);
  const __half* b = B + sBz * z + sBmod * (z % bmod);
  const int brow = blockIdx.y * TM;
  const int bcol = blockIdx.x * 128;

  int tid = threadIdx.x;
  int lane = tid & 31;
  int wid = tid >> 5;
  int wrow, wcol;
  if (TM == 128) { wrow = (wid & 3) * 32; wcol = (wid >> 2) * 64; }
  else           { wrow = (wid & 1) * 32; wcol = (wid >> 1) * 32; }

  uint32_t raw = smem_u32(dsm);
  uint32_t sb = (raw + 1023) & ~1023u;

  float acc[2][NI][4];
#pragma unroll
  for (int mi = 0; mi < 2; mi++)
#pragma unroll
    for (int ni = 0; ni < NI; ni++)
#pragma unroll
      for (int e = 0; e < 4; e++) acc[mi][ni][e] = 0.0f;

  int a_r  = (lane & 7) + ((lane >> 3) & 1) * 8;
  int a_k8 = ((lane >> 4) & 1) * 8;
  int b_r  = (lane & 7) + ((lane >> 4) & 1) * 8;
  int b_k8 = ((lane >> 3) & 1) * 8;

  load_chunk_h<TM>(sb, 0, 0, tid, brow, bcol, a, b); CP_COMMIT();
  load_chunk_h<TM>(sb, 1, 1, tid, brow, bcol, a, b); CP_COMMIT();

  for (int kc = 0; kc < 12; kc++) {
    if (kc < 11) { CP_WAIT(1); } else { CP_WAIT(0); }
    __syncthreads();

    uint32_t st = sb + (kc % 3) * STAGE;
    uint32_t tA = st;
    uint32_t tB = st + ASTAGE;

#pragma unroll
    for (int s = 0; s < 4; s++) {
      uint32_t fa[2][4];
#pragma unroll
      for (int mi = 0; mi < 2; mi++) {
        int r = wrow + mi * 16 + a_r;
        ldm4(fa[mi], tA + SWZ(r * 128 + (s * 16 + a_k8) * 2));
      }
#pragma unroll
      for (int p = 0; p < NPAIR; p++) {
        uint32_t fb[4][2];
#pragma unroll
        for (int nj2 = 0; nj2 < 2; nj2++) {
          int r = wcol + (p * 2 + nj2) * 16 + b_r;
          uint32_t t4[4];
          ldm4(t4, tB + SWZ(r * 128 + (s * 16 + b_k8) * 2));
          fb[nj2 * 2][0] = t4[0]; fb[nj2 * 2][1] = t4[1];
          fb[nj2 * 2 + 1][0] = t4[2]; fb[nj2 * 2 + 1][1] = t4[3];
        }
#pragma unroll
        for (int mi = 0; mi < 2; mi++)
#pragma unroll
          for (int nl = 0; nl < 4; nl++)
            mma16816h(acc[mi][p * 4 + nl], fa[mi], fb[nl]);
      }
    }

    if (kc + 2 < 12) {
      load_chunk_h<TM>(sb, (kc + 2) % 3, kc + 2, tid, brow, bcol, a, b);
      CP_COMMIT();
    }
  }

  __half* cof = Coutf16 + sCz * z;
  int qr = lane >> 2, qc = lane & 3;

#pragma unroll
  for (int mi = 0; mi < 2; mi++) {
#pragma unroll
    for (int ni = 0; ni < NI; ni++) {
      int gr0 = brow + wrow + mi * 16 + qr;
      int gc  = bcol + wcol + ni * 8 + qc * 2;
      *(uint32_t*)&cof[(ll)gr0 * ND + gc] =
          pack2h(__float2half(acc[mi][ni][0]), __float2half(acc[mi][ni][1]));
      *(uint32_t*)&cof[(ll)(gr0 + 8) * ND + gc] =
          pack2h(__float2half(acc[mi][ni][2]), __float2half(acc[mi][ni][3]));
    }
  }
}

// ---------------- merged setup (single launch) -------------------------------
// z=0: L_row -> Tf+S + Tsh/Tsl+S + Tf16+S    z=1: L_col -> +6S
// z=2: x -> xcur fp32 + Y16 slot0 fp16       z=3: W/U -> fp16 (32 blocks)
// z=4: x -> xT16 fp16 (transpose)
__global__ __launch_bounds__(256) void setup_kernel(
    const float* __restrict__ L_row, const float* __restrict__ L_col,
    float* __restrict__ Tf, __nv_bfloat16* __restrict__ Tsh,
    __nv_bfloat16* __restrict__ Tsl, __half* __restrict__ Tf16,
    const float* __restrict__ x, float* __restrict__ xcur,
    __half* __restrict__ Y16, __half* __restrict__ xT16,
    const float* __restrict__ Wf, const float* __restrict__ Uf,
    const float* __restrict__ Wi, const float* __restrict__ Ui,
    const float* __restrict__ Wo, const float* __restrict__ Uo,
    const float* __restrict__ Wc, const float* __restrict__ Uc,
    __half* __restrict__ Wt16)
{
  __shared__ float ts[32][33];
  int z = blockIdx.z;
  int t = threadIdx.x;

  if (z == 3) {
    if (blockIdx.x >= 32) return;
    const float* Ws[4] = {Wf, Wi, Wo, Wc};
    const float* Us[4] = {Uf, Ui, Uo, Uc};
    int idx = blockIdx.x * 256 + t;
    int n = idx >> 6, k = idx & 63;
    int g = n >> 5, o = n & 31;
    float v = (k < 32) ? Ws[g][k * 32 + o] : Us[g][(k - 32) * 32 + o];
    Wt16[idx] = __float2half(v);
    return;
  }
  if (z == 4) {
    int bx = (blockIdx.x % 24) * 32, by = (blockIdx.x / 24) * 32;
    int tx = t & 31, ty = t >> 5;
#pragma unroll
    for (int i = 0; i < 4; i++)
      ts[ty + 8 * i][tx] = x[(ll)(by + ty + 8 * i) * ND + bx + tx];
    __syncthreads();
#pragma unroll
    for (int i = 0; i < 4; i++)
      xT16[(ll)(bx + ty + 8 * i) * ND + by + tx] = __float2half(ts[tx][ty + 8 * i]);
    return;
  }
  if (z == 2) {
    int idx = blockIdx.x * 256 + t;
    float4 v = *(const float4*)(x + (ll)idx * 4);
    *(float4*)(xcur + (ll)idx * 4) = v;
    uint2 uf;
    uf.x = pack2h(__float2half(v.x), __float2half(v.y));
    uf.y = pack2h(__float2half(v.z), __float2half(v.w));
    *(uint2*)(Y16 + (ll)idx * 4) = uf;
    return;
  }

  const float* src = (z == 0) ? L_row : L_col;
  ll off = (z == 0) ? (ll)SZ : (ll)6 * SZ;
  int idx = blockIdx.x * 256 + t;
  float4 v = *(const float4*)(src + (ll)idx * 4);
  *(float4*)(Tf + off + (ll)idx * 4) = v;
  float a[4] = {v.x, v.y, v.z, v.w};
  __nv_bfloat16 h[4];
  uint2 uh, ul, uf;
#pragma unroll
  for (int e = 0; e < 4; e++) h[e] = __float2bfloat16(a[e]);
  uh.x = pack2(h[0], h[1]); uh.y = pack2(h[2], h[3]);
  ul.x = pack2(__float2bfloat16(a[0] - __bfloat162float(h[0])),
               __float2bfloat16(a[1] - __bfloat162float(h[1])));
  ul.y = pack2(__float2bfloat16(a[2] - __bfloat162float(h[2])),
               __float2bfloat16(a[3] - __bfloat162float(h[3])));
  uf.x = pack2h(__float2half(a[0]), __float2half(a[1]));
  uf.y = pack2h(__float2half(a[2]), __float2half(a[3]));
  *(uint2*)(Tsh + off + (ll)idx * 4) = uh;
  *(uint2*)(Tsl + off + (ll)idx * 4) = ul;
  *(uint2*)(Tf16 + off + (ll)idx * 4) = uf;
}

// ---------------- fused_rnn v7: fp16 1-term gates ----------------------------
// smem: A fp16 [128 pt][64 k] at 0 (16K, SW128; k 0-31 xc, 32-63 h)
//       W fp16 [128 n][64 k] at 16K (16K)
//       scalars at 32K: th 800f, bs 32f, swo 32f, sbg 128f
__device__ __forceinline__ float sigf(float v) {
  return __fdividef(1.0f, 1.0f + __expf(-v));
}

__global__ __launch_bounds__(256, 2) void fused_rnn(
    const __half* __restrict__ Y16_g, const __half* __restrict__ bf16_g,
    const float* __restrict__ theta, const float* __restrict__ bias,
    const __half* __restrict__ Wt16,
    const float* __restrict__ bf_, const float* __restrict__ bi_,
    const float* __restrict__ bo_, const float* __restrict__ bc_,
    const float* __restrict__ Wout, const float* __restrict__ bout,
    float* c, __half* h16_g, float* x,
    __half* __restrict__ xf16, __half* __restrict__ xT16,
    int first, int last)
{
  extern __shared__ char dsm[];
  uint32_t raw = smem_u32(dsm);
  uint32_t sb = (raw + 1023) & ~1023u;
  char* base = dsm + (sb - raw);

  float* th  = (float*)(base + 32768);
  float* bs  = (float*)(base + 32768 + 3200);
  float* swo = (float*)(base + 32768 + 3328);
  float* sbg = (float*)(base + 32768 + 3456);

  int t = threadIdx.x;
  int lane = t & 31;
  int w = t >> 5;
  size_t bpt = (size_t)blockIdx.x * 128;

  // ---- cp.async: W tile (.ca, shared across blocks) + h rows -----------------
#pragma unroll
  for (int i = 0; i < 4; i++) {          // W: 1024 chunks of 16B
    int idx = t + i * 256;
    int rr  = idx >> 3;
    int c4  = idx & 7;
    cpa16_ca(sb + 16384 + SWZ(rr * 128 + c4 * 16), Wt16 + rr * 64 + c4 * 8);
  }
  if (!first) {
#pragma unroll
    for (int i = 0; i < 2; i++) {        // h: 512 chunks into A cols 32..63
      int idx = t + i * 256;
      int rr  = idx >> 2;
      int c4h = (idx & 3) + 4;
      cpa16(sb + SWZ(rr * 128 + c4h * 16),
            h16_g + (bpt + rr) * 32 + (c4h - 4) * 8);
    }
  } else {
    uint4 z4 = make_uint4(0, 0, 0, 0);
#pragma unroll
    for (int i = 0; i < 2; i++) {
      int idx = t + i * 256;
      int rr  = idx >> 2;
      int c4h = (idx & 3) + 4;
      *(uint4*)(base + SWZ(rr * 128 + c4h * 16)) = z4;
    }
  }
  CP_COMMIT();

  // ---- prefetch 25 conv-source values (before any sync) ----------------------
  int r   = t & 127;
  int ohp = (t >> 7) * 16;
  size_t rg = bpt + r;
  float v[25];
  v[0] = __ldg(x + rg);
#pragma unroll
  for (int i = 1; i < 5; i++)
    v[i * 5] = __half2float(__ldg(Y16_g + (ll)i * SZ + rg));
#pragma unroll
  for (int i = 0; i < 5; i++)
#pragma unroll
    for (int j = 1; j < 5; j++)
      v[i * 5 + j] = __half2float(__ldg(bf16_g + (ll)(i * 4 + j - 1) * SZ + rg));

  // ---- scalars ---------------------------------------------------------------
  for (int i = t; i < 800; i += 256) th[i] = theta[i];
  if (t < 32) { bs[t] = bias[t]; swo[t] = Wout[t]; }
  if (t < 128) { const float* bx[4] = {bf_, bi_, bo_, bc_}; sbg[t] = bx[t >> 5][t & 31]; }
  __syncthreads();

  // ---- combine -> A cols 0..31 (xc fp16) -------------------------------------
  {
    float out[16];
#pragma unroll
    for (int o = 0; o < 16; o++) out[o] = bs[ohp + o];
#pragma unroll
    for (int ij = 0; ij < 25; ij++) {
      const float* tw = &th[ij * 32 + ohp];
#pragma unroll
      for (int o = 0; o < 16; o++) out[o] += v[ij] * tw[o];
    }
#pragma unroll
    for (int i = 0; i < 8; i++) {
      uint32_t byte = r * 128 + (ohp + 2 * i) * 2;
      *(uint32_t*)(base + SWZ(byte)) =
          pack2h(__float2half(out[2 * i]), __float2half(out[2 * i + 1]));
    }
  }
  CP_WAIT(0);
  __syncthreads();

  // ---- HMMA: PRE[128 pt x 128 n] = A @ W^T (fp16 single-term) ----------------
  int a_r  = (lane & 7) + ((lane >> 3) & 1) * 8;
  int a_k8 = ((lane >> 4) & 1) * 8;
  int b_r  = (lane & 7) + ((lane >> 4) & 1) * 8;
  int b_k8 = ((lane >> 3) & 1) * 8;

  float acc[16][4];
#pragma unroll
  for (int nt = 0; nt < 16; nt++)
#pragma unroll
    for (int e = 0; e < 4; e++) acc[nt][e] = 0.0f;

#pragma unroll
  for (int ks = 0; ks < 4; ks++) {
    uint32_t ah4[4];
    ldm4(ah4, sb + SWZ((w * 16 + a_r) * 128 + (ks * 16 + a_k8) * 2));
#pragma unroll
    for (int np = 0; np < 8; np++) {
      uint32_t bh4[4];
      ldm4(bh4, sb + 16384 + SWZ((np * 16 + b_r) * 128 + (ks * 16 + b_k8) * 2));
      mma16816h(acc[2 * np],     ah4, bh4);
      mma16816h(acc[2 * np + 1], ah4, bh4 + 2);
    }
  }

  // ---- in-register gates + c/h update + dx partials --------------------------
  int qr = lane >> 2, qc = lane & 3;
  size_t p0 = bpt + w * 16 + qr;
  float pd[2] = {0.0f, 0.0f};

#pragma unroll
  for (int m = 0; m < 4; m++) {
#pragma unroll
    for (int rh = 0; rh < 2; rh++) {
      size_t pt = p0 + 8 * rh;
      int ob = 8 * m + 2 * qc;
      float2 cold = make_float2(0.0f, 0.0f);
      if (!first) cold = *(const float2*)&c[pt * 32 + ob];
      float cn[2], hn[2];
#pragma unroll
      for (int p = 0; p < 2; p++) {
        int o = ob + p;
        int e = p + 2 * rh;
        float zi = acc[4 + m][e]  + sbg[32 + o];
        float zc = acc[12 + m][e] + sbg[96 + o];
        float cnew = sigf(zi) * sigf(zc);
        if (!first) {
          float zf = acc[m][e] + sbg[o];
          cnew += sigf(zf) * (p ? cold.y : cold.x);
        }
        cn[p] = cnew;
        pd[rh] += cnew * swo[o];
        if (!last) {
          float zo = acc[8 + m][e] + sbg[64 + o];
          hn[p] = sigf(zo) * sigf(cnew);
        }
      }
      if (!last) {
        *(float2*)&c[pt * 32 + ob] = make_float2(cn[0], cn[1]);
        *(uint32_t*)&h16_g[pt * 32 + ob] =
            pack2h(__float2half(hn[0]), __float2half(hn[1]));
      }
    }
  }

#pragma unroll
  for (int rh = 0; rh < 2; rh++) {
    pd[rh] += __shfl_xor_sync(0xFFFFFFFF, pd[rh], 1);
    pd[rh] += __shfl_xor_sync(0xFFFFFFFF, pd[rh], 2);
  }
  if (qc == 0) {
    float b0 = __ldg(bout);
#pragma unroll
    for (int rh = 0; rh < 2; rh++) {
      size_t gi = p0 + 8 * rh;
      float xn = x[gi] + tanhf(pd[rh] + b0);
      x[gi] = xn;
      if (!last) {
        __half xh = __float2half(xn);
        xf16[gi] = xh;
        int row = (int)(gi / ND);
        int col = (int)(gi - (size_t)row * ND);
        xT16[(ll)col * ND + row] = xh;
      }
    }
  }
}

// ---------------- orchestration ----------------------------------------------
extern "C" void kernel_launch(void* const* d_in, const int* in_sizes, int n_in,
                              void* d_out, int out_size)
{
  const float* x     = (const float*)d_in[0];
  const float* L_row = (const float*)d_in[1];
  const float* L_col = (const float*)d_in[2];
  const float* theta = (const float*)d_in[3];
  const float* bias  = (const float*)d_in[4];
  const float* W_f = (const float*)d_in[5];
  const float* U_f = (const float*)d_in[6];
  const float* b_f = (const float*)d_in[7];
  const float* W_i = (const float*)d_in[8];
  const float* U_i = (const float*)d_in[9];
  const float* b_i = (const float*)d_in[10];
  const float* W_o = (const float*)d_in[11];
  const float* U_o = (const float*)d_in[12];
  const float* b_o = (const float*)d_in[13];
  const float* W_c = (const float*)d_in[14];
  const float* U_c = (const float*)d_in[15];
  const float* b_c = (const float*)d_in[16];
  const float* W_out = (const float*)d_in[17];
  const float* b_out = (const float*)d_in[18];
  // d_in[19] = nb_iterations_rnn = 3 (fixed by setup)

  float* xcur = (float*)d_out;

  float *Tf, *c;
  __nv_bfloat16 *Tsh, *Tsl;
  __half *Tf16, *xT16, *Y16, *bf16, *h16, *Wt16;
  cudaGetSymbolAddress((void**)&Tf,   g_Tf);
  cudaGetSymbolAddress((void**)&Tsh,  g_Tsh);
  cudaGetSymbolAddress((void**)&Tsl,  g_Tsl);
  cudaGetSymbolAddress((void**)&Tf16, g_Tf16);
  cudaGetSymbolAddress((void**)&xT16, g_xT16);
  cudaGetSymbolAddress((void**)&Y16,  g_Y16);
  cudaGetSymbolAddress((void**)&bf16, g_bf16);
  cudaGetSymbolAddress((void**)&h16,  g_h16);
  cudaGetSymbolAddress((void**)&c,    g_c);
  cudaGetSymbolAddress((void**)&Wt16, g_Wt16);

  const ll S = SZ;
  const int DSM_CHEB = 1024 + 3 * 49152;               // bf16 3-term, 48KB stages
  const int DSM_Y    = 1024 + 3 * ((64 + 128) * 128);  // fp16, 24KB stages
  const int DSM_BF   = 1024 + 3 * ((128 + 128) * 128); // fp16, 32KB stages
  const int FSM      = 1024 + 32768 + 3968;
  cudaFuncSetAttribute((const void*)tc_gemm_cheb,   cudaFuncAttributeMaxDynamicSharedMemorySize, DSM_CHEB);
  cudaFuncSetAttribute((const void*)tc_gemm16<64>,  cudaFuncAttributeMaxDynamicSharedMemorySize, DSM_Y);
  cudaFuncSetAttribute((const void*)tc_gemm16<128>, cudaFuncAttributeMaxDynamicSharedMemorySize, DSM_BF);
  cudaFuncSetAttribute((const void*)fused_rnn,      cudaFuncAttributeMaxDynamicSharedMemorySize, FSM);

  // launch 1: merged setup
  {
    dim3 g(SZ / 1024, 1, 5);
    setup_kernel<<<g, 256>>>(L_row, L_col, Tf, Tsh, Tsl, Tf16,
                             x, xcur, Y16, xT16,
                             W_f, U_f, W_i, U_i, W_o, U_o, W_c, U_c, Wt16);
  }

  // Chebyshev recursion (bf16 3-term; emits fp32 + bf16 split + fp16)
  for (int k = 2; k <= 4; k++) {
    dim3 g(6, 12, 2);
    int cinmode = (k == 2) ? 1 : 2;
    const float* cin = (k == 2) ? (const float*)0 : (Tf + (ll)(k - 2) * S);
    tc_gemm_cheb<<<g, 256, DSM_CHEB>>>(
        Tsh + S, Tsl + S,
        Tsh + (ll)(k - 1) * S, Tsl + (ll)(k - 1) * S,
        cin, Tf + (ll)k * S, Tsh + (ll)k * S, Tsl + (ll)k * S, Tf16 + (ll)k * S,
        5 * S, 5 * S, 5 * S, 5 * S, 2.0f, -1.0f, cinmode);
  }

  for (int it = 0; it < 3; it++) {
    // Y_{1+z} = Tr_{1+z} @ x   (fp16 single-term, fp16 out)
    {
      dim3 g(6, 12, 4);
      tc_gemm16<64><<<g, 256, DSM_Y>>>(
          Tf16 + S, xT16, Y16 + S,
          S, 0, 1,    0, 0, 1,    S);
    }
    // bf[z] = Y_{z/4} @ Tc_{1+z%4}   (fp16 single-term, fp16 out)
    {
      dim3 g(6, 6, 20);
      tc_gemm16<128><<<g, 256, DSM_BF>>>(
          Y16, Tf16 + 6 * S, bf16,
          0, S, 4,    0, S, 4,    S);
    }
    fused_rnn<<<SZ / 128, 256, FSM>>>(
        Y16, bf16, theta, bias, Wt16,
        b_f, b_i, b_o, b_c, W_out, b_out,
        c, h16, xcur, Y16, xT16,
        (it == 0) ? 1 : 0, (it == 2) ? 1 : 0);
  }
}

// round 14
// speedup vs baseline: 1.6209x; 1.0227x over previous
#include <cuda_runtime.h>
#include <cuda_bf16.h>
#include <cuda_fp16.h>
#include <cstdint>

#define ND 768
#define SZ (768*768)
#define MNTOT SZ
typedef long long ll;

// ---------------- scratch (device globals) ----------------------------------
__device__ float g_Tf[10*SZ];                         // fp32 T[side][k]
__device__ __align__(16) __nv_bfloat16 g_Tsh[10*SZ];  // bf16 hi (cheb)
__device__ __align__(16) __nv_bfloat16 g_Tsl[10*SZ];  // bf16 lo (cheb)
__device__ __align__(16) __half g_Tf16[10*SZ];        // fp16 T (Y/bf operands)
__device__ __align__(16) __half g_xT16[SZ];           // fp16 x^T
__device__ __align__(16) __half g_Y16[5*SZ];          // slot0 = x fp16; 1..4 = Y_i
__device__ __align__(16) __half g_bf16[20*SZ];        // bf products fp16
__device__ __align__(16) __half g_h16[32*SZ];         // h point-major [pt][32] fp16
__device__ __align__(16) __half g_c16[32*SZ];         // c point-major [pt][32] fp16
__device__ __align__(16) __half g_Wt16[128*64];       // [n=g*32+o][k] fp16

// ---------------- helpers -----------------------------------------------------
#define SWZ(x)   ((x) ^ (((x) >> 3) & 0x70))   // 128B rows

__device__ __forceinline__ uint32_t smem_u32(const void* p) {
  uint32_t a;
  asm("{ .reg .u64 t; cvta.to.shared.u64 t, %1; cvt.u32.u64 %0, t; }"
      : "=r"(a) : "l"(p));
  return a;
}

__device__ __forceinline__ void cpa16(uint32_t dst, const void* src) {
  asm volatile("cp.async.cg.shared.global [%0], [%1], 16;"
               :: "r"(dst), "l"(src) : "memory");
}
__device__ __forceinline__ void cpa16_ca(uint32_t dst, const void* src) {
  asm volatile("cp.async.ca.shared.global [%0], [%1], 16;"
               :: "r"(dst), "l"(src) : "memory");
}
#define CP_COMMIT() asm volatile("cp.async.commit_group;" ::: "memory")
#define CP_WAIT(n)  asm volatile("cp.async.wait_group %0;" :: "n"(n) : "memory")

__device__ __forceinline__ void ldm4(uint32_t* r, uint32_t addr) {
  asm volatile("ldmatrix.sync.aligned.m8n8.x4.shared.b16 {%0,%1,%2,%3}, [%4];"
               : "=r"(r[0]), "=r"(r[1]), "=r"(r[2]), "=r"(r[3]) : "r"(addr));
}

__device__ __forceinline__ void mma16816(float* c, const uint32_t* a,
                                         const uint32_t* b) {
  asm volatile(
      "mma.sync.aligned.m16n8k16.row.col.f32.bf16.bf16.f32 "
      "{%0,%1,%2,%3},{%4,%5,%6,%7},{%8,%9},{%0,%1,%2,%3};"
      : "+f"(c[0]), "+f"(c[1]), "+f"(c[2]), "+f"(c[3])
      : "r"(a[0]), "r"(a[1]), "r"(a[2]), "r"(a[3]), "r"(b[0]), "r"(b[1]));
}

__device__ __forceinline__ void mma16816h(float* c, const uint32_t* a,
                                          const uint32_t* b) {
  asm volatile(
      "mma.sync.aligned.m16n8k16.row.col.f32.f16.f16.f32 "
      "{%0,%1,%2,%3},{%4,%5,%6,%7},{%8,%9},{%0,%1,%2,%3};"
      : "+f"(c[0]), "+f"(c[1]), "+f"(c[2]), "+f"(c[3])
      : "r"(a[0]), "r"(a[1]), "r"(a[2]), "r"(a[3]), "r"(b[0]), "r"(b[1]));
}

__device__ __forceinline__ uint32_t pack2(__nv_bfloat16 a, __nv_bfloat16 b) {
  __nv_bfloat162 t(a, b);
  return *reinterpret_cast<uint32_t*>(&t);
}
__device__ __forceinline__ uint32_t pack2h(__half a, __half b) {
  __half2 t(a, b);
  return *reinterpret_cast<uint32_t*>(&t);
}

// ================= bf16 3-term GEMM (Chebyshev only) =========================
__device__ __forceinline__ void load_chunk_b(
    uint32_t sb, int s, int kc, int tid, int brow, int bcol,
    const __nv_bfloat16* a0, const __nv_bfloat16* a1,
    const __nv_bfloat16* b0, const __nv_bfloat16* b1)
{
  constexpr int ASTAGE = 64 * 128;
  constexpr int BSTAGE = 128 * 128;
  constexpr int STAGE  = 2 * ASTAGE + 2 * BSTAGE;   // 48 KB
#pragma unroll
  for (int i = 0; i < 12; i++) {
    int idx = tid + i * 256;
    int cc = idx & 7;
    int rowIdx = idx >> 3;
    const __nv_bfloat16* src;
    uint32_t dstbase;
    if (rowIdx < 128) {
      int mat = rowIdx >> 6;
      int row = rowIdx & 63;
      src = (mat ? a1 : a0) + (ll)(brow + row) * ND + kc * 64 + cc * 8;
      dstbase = mat * ASTAGE + SWZ(row * 128 + cc * 16);
    } else {
      int rr = rowIdx - 128;
      int mat = rr >> 7;
      int row = rr & 127;
      src = (mat ? b1 : b0) + (ll)(bcol + row) * ND + kc * 64 + cc * 8;
      dstbase = 2 * ASTAGE + mat * BSTAGE + SWZ(row * 128 + cc * 16);
    }
    cpa16(sb + s * STAGE + dstbase, src);
  }
}

__global__ __launch_bounds__(256, 1) void tc_gemm_cheb(
    const __nv_bfloat16* __restrict__ Ah, const __nv_bfloat16* __restrict__ Al,
    const __nv_bfloat16* __restrict__ Bh, const __nv_bfloat16* __restrict__ Bl,
    const float* __restrict__ Cin, float* __restrict__ Cout,
    __nv_bfloat16* __restrict__ Couth, __nv_bfloat16* __restrict__ Coutl,
    __half* __restrict__ Coutf16,
    ll sAz, ll sBz, ll sCinz, ll sCz, float alpha, float beta, int cinmode)
{
  extern __shared__ char dsm[];
  constexpr int ASTAGE = 64 * 128;
  constexpr int BSTAGE = 128 * 128;
  constexpr int STAGE  = 2 * ASTAGE + 2 * BSTAGE;

  int z = blockIdx.z;
  const __nv_bfloat16* ah = Ah + sAz * z;
  const __nv_bfloat16* al = Al + sAz * z;
  const __nv_bfloat16* bh = Bh + sBz * z;
  const __nv_bfloat16* bl = Bl + sBz * z;
  const int brow = blockIdx.y * 64;
  const int bcol = blockIdx.x * 128;

  int tid = threadIdx.x;
  int lane = tid & 31;
  int wid = tid >> 5;
  int wrow = (wid & 1) * 32;
  int wcol = (wid >> 1) * 32;

  uint32_t raw = smem_u32(dsm);
  uint32_t sb = (raw + 1023) & ~1023u;

  float acc[2][4][4];
#pragma unroll
  for (int mi = 0; mi < 2; mi++)
#pragma unroll
    for (int ni = 0; ni < 4; ni++)
#pragma unroll
      for (int e = 0; e < 4; e++) acc[mi][ni][e] = 0.0f;

  int a_r  = (lane & 7) + ((lane >> 3) & 1) * 8;
  int a_k8 = ((lane >> 4) & 1) * 8;
  int b_r  = (lane & 7) + ((lane >> 4) & 1) * 8;
  int b_k8 = ((lane >> 3) & 1) * 8;

  load_chunk_b(sb, 0, 0, tid, brow, bcol, ah, al, bh, bl); CP_COMMIT();
  load_chunk_b(sb, 1, 1, tid, brow, bcol, ah, al, bh, bl); CP_COMMIT();

  for (int kc = 0; kc < 12; kc++) {
    if (kc < 11) { CP_WAIT(1); } else { CP_WAIT(0); }
    __syncthreads();

    uint32_t st  = sb + (kc % 3) * STAGE;
    uint32_t tAh = st;
    uint32_t tAl = st + ASTAGE;
    uint32_t tBh = st + 2 * ASTAGE;
    uint32_t tBl = tBh + BSTAGE;

#pragma unroll
    for (int s = 0; s < 4; s++) {
      uint32_t fah[2][4], fal[2][4];
#pragma unroll
      for (int mi = 0; mi < 2; mi++) {
        int r = wrow + mi * 16 + a_r;
        uint32_t off = SWZ(r * 128 + (s * 16 + a_k8) * 2);
        ldm4(fah[mi], tAh + off);
        ldm4(fal[mi], tAl + off);
      }
      uint32_t fbh[4][2], fbl[4][2];
#pragma unroll
      for (int nj2 = 0; nj2 < 2; nj2++) {
        int r = wcol + nj2 * 16 + b_r;
        uint32_t off = SWZ(r * 128 + (s * 16 + b_k8) * 2);
        uint32_t t4[4];
        ldm4(t4, tBh + off);
        fbh[nj2 * 2][0] = t4[0]; fbh[nj2 * 2][1] = t4[1];
        fbh[nj2 * 2 + 1][0] = t4[2]; fbh[nj2 * 2 + 1][1] = t4[3];
        ldm4(t4, tBl + off);
        fbl[nj2 * 2][0] = t4[0]; fbl[nj2 * 2][1] = t4[1];
        fbl[nj2 * 2 + 1][0] = t4[2]; fbl[nj2 * 2 + 1][1] = t4[3];
      }
#pragma unroll
      for (int mi = 0; mi < 2; mi++)
#pragma unroll
        for (int nl = 0; nl < 4; nl++)
          mma16816(acc[mi][nl], fah[mi], fbh[nl]);
#pragma unroll
      for (int mi = 0; mi < 2; mi++)
#pragma unroll
        for (int nl = 0; nl < 4; nl++)
          mma16816(acc[mi][nl], fah[mi], fbl[nl]);
#pragma unroll
      for (int mi = 0; mi < 2; mi++)
#pragma unroll
        for (int nl = 0; nl < 4; nl++)
          mma16816(acc[mi][nl], fal[mi], fbh[nl]);
    }

    if (kc + 2 < 12) {
      load_chunk_b(sb, (kc + 2) % 3, kc + 2, tid, brow, bcol, ah, al, bh, bl);
      CP_COMMIT();
    }
  }

  const float* cinp = (cinmode == 2) ? (Cin + sCinz * z) : (const float*)0;
  float* co = Cout + sCz * z;
  __nv_bfloat16* coh = Couth + sCz * z;
  __nv_bfloat16* col = Coutl + sCz * z;
  __half* cof = Coutf16 + sCz * z;
  int qr = lane >> 2, qc = lane & 3;

#pragma unroll
  for (int mi = 0; mi < 2; mi++) {
#pragma unroll
    for (int ni = 0; ni < 4; ni++) {
      int gr0 = brow + wrow + mi * 16 + qr;
      int gc  = bcol + wcol + ni * 8 + qc * 2;
      float2 v0, v1;
      v0.x = alpha * acc[mi][ni][0];
      v0.y = alpha * acc[mi][ni][1];
      v1.x = alpha * acc[mi][ni][2];
      v1.y = alpha * acc[mi][ni][3];
      if (cinmode == 2) {
        float2 c0 = *(const float2*)&cinp[(ll)gr0 * ND + gc];
        float2 c1 = *(const float2*)&cinp[(ll)(gr0 + 8) * ND + gc];
        v0.x += beta * c0.x; v0.y += beta * c0.y;
        v1.x += beta * c1.x; v1.y += beta * c1.y;
      } else if (cinmode == 1) {
        if (gr0 == gc)         v0.x += beta;
        if (gr0 == gc + 1)     v0.y += beta;
        if (gr0 + 8 == gc)     v1.x += beta;
        if (gr0 + 8 == gc + 1) v1.y += beta;
      }
      *(float2*)&co[(ll)gr0 * ND + gc]       = v0;
      *(float2*)&co[(ll)(gr0 + 8) * ND + gc] = v1;
      __nv_bfloat16 h0 = __float2bfloat16(v0.x);
      __nv_bfloat16 h1 = __float2bfloat16(v0.y);
      __nv_bfloat16 h2 = __float2bfloat16(v1.x);
      __nv_bfloat16 h3 = __float2bfloat16(v1.y);
      *(uint32_t*)&coh[(ll)gr0 * ND + gc]       = pack2(h0, h1);
      *(uint32_t*)&coh[(ll)(gr0 + 8) * ND + gc] = pack2(h2, h3);
      *(uint32_t*)&col[(ll)gr0 * ND + gc] =
          pack2(__float2bfloat16(v0.x - __bfloat162float(h0)),
                __float2bfloat16(v0.y - __bfloat162float(h1)));
      *(uint32_t*)&col[(ll)(gr0 + 8) * ND + gc] =
          pack2(__float2bfloat16(v1.x - __bfloat162float(h2)),
                __float2bfloat16(v1.y - __bfloat162float(h3)));
      *(uint32_t*)&cof[(ll)gr0 * ND + gc] =
          pack2h(__float2half(v0.x), __float2half(v0.y));
      *(uint32_t*)&cof[(ll)(gr0 + 8) * ND + gc] =
          pack2h(__float2half(v1.x), __float2half(v1.y));
    }
  }
}

// ================= fp16 single-term GEMM (Y and bf) ==========================
template<int TM>
__device__ __forceinline__ void load_chunk_h(
    uint32_t sb, int s, int kc, int tid, int brow, int bcol,
    const __half* a, const __half* b)
{
  constexpr int ASTAGE = TM * 128;
  constexpr int STAGE  = ASTAGE + 128 * 128;
  constexpr int ITER   = (TM + 128) * 8 / 256;
#pragma unroll
  for (int i = 0; i < ITER; i++) {
    int idx = tid + i * 256;
    int cc = idx & 7;
    int rowIdx = idx >> 3;
    const __half* src;
    uint32_t dstbase;
    if (rowIdx < TM) {
      src = a + (ll)(brow + rowIdx) * ND + kc * 64 + cc * 8;
      dstbase = SWZ(rowIdx * 128 + cc * 16);
    } else {
      int row = rowIdx - TM;
      src = b + (ll)(bcol + row) * ND + kc * 64 + cc * 8;
      dstbase = ASTAGE + SWZ(row * 128 + cc * 16);
    }
    cpa16(sb + s * STAGE + dstbase, src);
  }
}

template<int TM>
__global__ __launch_bounds__(256, 2) void tc_gemm16(
    const __half* __restrict__ A, const __half* __restrict__ B,
    __half* __restrict__ Coutf16,
    ll sAz, ll sAdiv, int adiv,
    ll sBz, ll sBmod, int bmod, ll sCz)
{
  extern __shared__ char dsm[];
  constexpr int ASTAGE = TM * 128;
  constexpr int STAGE  = ASTAGE + 128 * 128;
  constexpr int NI = (TM == 128) ? 8 : 4;
  constexpr int NPAIR = NI / 4;

  int z = blockIdx.z;
  const __half* a = A + sAz * z + sAdiv * (z / adiv);
  const __half* b = B + sBz * z + sBmod * (z % bmod);
  const int brow = blockIdx.y * TM;
  const int bcol = blockIdx.x * 128;

  int tid = threadIdx.x;
  int lane = tid & 31;
  int wid = tid >> 5;
  int wrow, wcol;
  if (TM == 128) { wrow = (wid & 3) * 32; wcol = (wid >> 2) * 64; }
  else           { wrow = (wid & 1) * 32; wcol = (wid >> 1) * 32; }

  uint32_t raw = smem_u32(dsm);
  uint32_t sb = (raw + 1023) & ~1023u;

  float acc[2][NI][4];
#pragma unroll
  for (int mi = 0; mi < 2; mi++)
#pragma unroll
    for (int ni = 0; ni < NI; ni++)
#pragma unroll
      for (int e = 0; e < 4; e++) acc[mi][ni][e] = 0.0f;

  int a_r  = (lane & 7) + ((lane >> 3) & 1) * 8;
  int a_k8 = ((lane >> 4) & 1) * 8;
  int b_r  = (lane & 7) + ((lane >> 4) & 1) * 8;
  int b_k8 = ((lane >> 3) & 1) * 8;

  load_chunk_h<TM>(sb, 0, 0, tid, brow, bcol, a, b); CP_COMMIT();
  load_chunk_h<TM>(sb, 1, 1, tid, brow, bcol, a, b); CP_COMMIT();

  for (int kc = 0; kc < 12; kc++) {
    if (kc < 11) { CP_WAIT(1); } else { CP_WAIT(0); }
    __syncthreads();

    uint32_t st = sb + (kc % 3) * STAGE;
    uint32_t tA = st;
    uint32_t tB = st + ASTAGE;

#pragma unroll
    for (int s = 0; s < 4; s++) {
      uint32_t fa[2][4];
#pragma unroll
      for (int mi = 0; mi < 2; mi++) {
        int r = wrow + mi * 16 + a_r;
        ldm4(fa[mi], tA + SWZ(r * 128 + (s * 16 + a_k8) * 2));
      }
#pragma unroll
      for (int p = 0; p < NPAIR; p++) {
        uint32_t fb[4][2];
#pragma unroll
        for (int nj2 = 0; nj2 < 2; nj2++) {
          int r = wcol + (p * 2 + nj2) * 16 + b_r;
          uint32_t t4[4];
          ldm4(t4, tB + SWZ(r * 128 + (s * 16 + b_k8) * 2));
          fb[nj2 * 2][0] = t4[0]; fb[nj2 * 2][1] = t4[1];
          fb[nj2 * 2 + 1][0] = t4[2]; fb[nj2 * 2 + 1][1] = t4[3];
        }
#pragma unroll
        for (int mi = 0; mi < 2; mi++)
#pragma unroll
          for (int nl = 0; nl < 4; nl++)
            mma16816h(acc[mi][p * 4 + nl], fa[mi], fb[nl]);
      }
    }

    if (kc + 2 < 12) {
      load_chunk_h<TM>(sb, (kc + 2) % 3, kc + 2, tid, brow, bcol, a, b);
      CP_COMMIT();
    }
  }

  __half* cof = Coutf16 + sCz * z;
  int qr = lane >> 2, qc = lane & 3;

#pragma unroll
  for (int mi = 0; mi < 2; mi++) {
#pragma unroll
    for (int ni = 0; ni < NI; ni++) {
      int gr0 = brow + wrow + mi * 16 + qr;
      int gc  = bcol + wcol + ni * 8 + qc * 2;
      *(uint32_t*)&cof[(ll)gr0 * ND + gc] =
          pack2h(__float2half(acc[mi][ni][0]), __float2half(acc[mi][ni][1]));
      *(uint32_t*)&cof[(ll)(gr0 + 8) * ND + gc] =
          pack2h(__float2half(acc[mi][ni][2]), __float2half(acc[mi][ni][3]));
    }
  }
}

// ---------------- merged setup (single launch) -------------------------------
__global__ __launch_bounds__(256) void setup_kernel(
    const float* __restrict__ L_row, const float* __restrict__ L_col,
    float* __restrict__ Tf, __nv_bfloat16* __restrict__ Tsh,
    __nv_bfloat16* __restrict__ Tsl, __half* __restrict__ Tf16,
    const float* __restrict__ x, float* __restrict__ xcur,
    __half* __restrict__ Y16, __half* __restrict__ xT16,
    const float* __restrict__ Wf, const float* __restrict__ Uf,
    const float* __restrict__ Wi, const float* __restrict__ Ui,
    const float* __restrict__ Wo, const float* __restrict__ Uo,
    const float* __restrict__ Wc, const float* __restrict__ Uc,
    __half* __restrict__ Wt16)
{
  __shared__ float ts[32][33];
  int z = blockIdx.z;
  int t = threadIdx.x;

  if (z == 3) {
    if (blockIdx.x >= 32) return;
    const float* Ws[4] = {Wf, Wi, Wo, Wc};
    const float* Us[4] = {Uf, Ui, Uo, Uc};
    int idx = blockIdx.x * 256 + t;
    int n = idx >> 6, k = idx & 63;
    int g = n >> 5, o = n & 31;
    float v = (k < 32) ? Ws[g][k * 32 + o] : Us[g][(k - 32) * 32 + o];
    Wt16[idx] = __float2half(v);
    return;
  }
  if (z == 4) {
    int bx = (blockIdx.x % 24) * 32, by = (blockIdx.x / 24) * 32;
    int tx = t & 31, ty = t >> 5;
#pragma unroll
    for (int i = 0; i < 4; i++)
      ts[ty + 8 * i][tx] = x[(ll)(by + ty + 8 * i) * ND + bx + tx];
    __syncthreads();
#pragma unroll
    for (int i = 0; i < 4; i++)
      xT16[(ll)(bx + ty + 8 * i) * ND + by + tx] = __float2half(ts[tx][ty + 8 * i]);
    return;
  }
  if (z == 2) {
    int idx = blockIdx.x * 256 + t;
    float4 v = *(const float4*)(x + (ll)idx * 4);
    *(float4*)(xcur + (ll)idx * 4) = v;
    uint2 uf;
    uf.x = pack2h(__float2half(v.x), __float2half(v.y));
    uf.y = pack2h(__float2half(v.z), __float2half(v.w));
    *(uint2*)(Y16 + (ll)idx * 4) = uf;
    return;
  }

  const float* src = (z == 0) ? L_row : L_col;
  ll off = (z == 0) ? (ll)SZ : (ll)6 * SZ;
  int idx = blockIdx.x * 256 + t;
  float4 v = *(const float4*)(src + (ll)idx * 4);
  *(float4*)(Tf + off + (ll)idx * 4) = v;
  float a[4] = {v.x, v.y, v.z, v.w};
  __nv_bfloat16 h[4];
  uint2 uh, ul, uf;
#pragma unroll
  for (int e = 0; e < 4; e++) h[e] = __float2bfloat16(a[e]);
  uh.x = pack2(h[0], h[1]); uh.y = pack2(h[2], h[3]);
  ul.x = pack2(__float2bfloat16(a[0] - __bfloat162float(h[0])),
               __float2bfloat16(a[1] - __bfloat162float(h[1])));
  ul.y = pack2(__float2bfloat16(a[2] - __bfloat162float(h[2])),
               __float2bfloat16(a[3] - __bfloat162float(h[3])));
  uf.x = pack2h(__float2half(a[0]), __float2half(a[1]));
  uf.y = pack2h(__float2half(a[2]), __float2half(a[3]));
  *(uint2*)(Tsh + off + (ll)idx * 4) = uh;
  *(uint2*)(Tsl + off + (ll)idx * 4) = ul;
  *(uint2*)(Tf16 + off + (ll)idx * 4) = uf;
}

// ---------------- fused_rnn v8: fp16 gates + fp16 c --------------------------
__device__ __forceinline__ float sigf(float v) {
  return __fdividef(1.0f, 1.0f + __expf(-v));
}

__global__ __launch_bounds__(256, 2) void fused_rnn(
    const __half* __restrict__ Y16_g, const __half* __restrict__ bf16_g,
    const float* __restrict__ theta, const float* __restrict__ bias,
    const __half* __restrict__ Wt16,
    const float* __restrict__ bf_, const float* __restrict__ bi_,
    const float* __restrict__ bo_, const float* __restrict__ bc_,
    const float* __restrict__ Wout, const float* __restrict__ bout,
    __half* c16, __half* h16_g, float* x,
    __half* __restrict__ xf16, __half* __restrict__ xT16,
    int first, int last)
{
  extern __shared__ char dsm[];
  uint32_t raw = smem_u32(dsm);
  uint32_t sb = (raw + 1023) & ~1023u;
  char* base = dsm + (sb - raw);

  float* th  = (float*)(base + 32768);
  float* bs  = (float*)(base + 32768 + 3200);
  float* swo = (float*)(base + 32768 + 3328);
  float* sbg = (float*)(base + 32768 + 3456);

  int t = threadIdx.x;
  int lane = t & 31;
  int w = t >> 5;
  size_t bpt = (size_t)blockIdx.x * 128;

  // ---- cp.async: W tile (.ca) + h rows ---------------------------------------
#pragma unroll
  for (int i = 0; i < 4; i++) {
    int idx = t + i * 256;
    int rr  = idx >> 3;
    int c4  = idx & 7;
    cpa16_ca(sb + 16384 + SWZ(rr * 128 + c4 * 16), Wt16 + rr * 64 + c4 * 8);
  }
  if (!first) {
#pragma unroll
    for (int i = 0; i < 2; i++) {
      int idx = t + i * 256;
      int rr  = idx >> 2;
      int c4h = (idx & 3) + 4;
      cpa16(sb + SWZ(rr * 128 + c4h * 16),
            h16_g + (bpt + rr) * 32 + (c4h - 4) * 8);
    }
  } else {
    uint4 z4 = make_uint4(0, 0, 0, 0);
#pragma unroll
    for (int i = 0; i < 2; i++) {
      int idx = t + i * 256;
      int rr  = idx >> 2;
      int c4h = (idx & 3) + 4;
      *(uint4*)(base + SWZ(rr * 128 + c4h * 16)) = z4;
    }
  }
  CP_COMMIT();

  // ---- prefetch 25 conv-source values (fp16, before any sync) ----------------
  int r   = t & 127;
  int ohp = (t >> 7) * 16;
  size_t rg = bpt + r;
  float v[25];
#pragma unroll
  for (int i = 0; i < 5; i++)
    v[i * 5] = __half2float(__ldg(Y16_g + (ll)i * SZ + rg));
#pragma unroll
  for (int i = 0; i < 5; i++)
#pragma unroll
    for (int j = 1; j < 5; j++)
      v[i * 5 + j] = __half2float(__ldg(bf16_g + (ll)(i * 4 + j - 1) * SZ + rg));

  // ---- scalars ---------------------------------------------------------------
  for (int i = t; i < 800; i += 256) th[i] = theta[i];
  if (t < 32) { bs[t] = bias[t]; swo[t] = Wout[t]; }
  if (t < 128) { const float* bx[4] = {bf_, bi_, bo_, bc_}; sbg[t] = bx[t >> 5][t & 31]; }
  __syncthreads();

  // ---- combine -> A cols 0..31 (xc fp16) -------------------------------------
  {
    float out[16];
#pragma unroll
    for (int o = 0; o < 16; o++) out[o] = bs[ohp + o];
#pragma unroll
    for (int ij = 0; ij < 25; ij++) {
      const float* tw = &th[ij * 32 + ohp];
#pragma unroll
      for (int o = 0; o < 16; o++) out[o] += v[ij] * tw[o];
    }
#pragma unroll
    for (int i = 0; i < 8; i++) {
      uint32_t byte = r * 128 + (ohp + 2 * i) * 2;
      *(uint32_t*)(base + SWZ(byte)) =
          pack2h(__float2half(out[2 * i]), __float2half(out[2 * i + 1]));
    }
  }
  CP_WAIT(0);
  __syncthreads();

  // ---- HMMA: PRE[128 pt x 128 n] = A @ W^T (fp16 single-term) ----------------
  int a_r  = (lane & 7) + ((lane >> 3) & 1) * 8;
  int a_k8 = ((lane >> 4) & 1) * 8;
  int b_r  = (lane & 7) + ((lane >> 4) & 1) * 8;
  int b_k8 = ((lane >> 3) & 1) * 8;

  float acc[16][4];
#pragma unroll
  for (int nt = 0; nt < 16; nt++)
#pragma unroll
    for (int e = 0; e < 4; e++) acc[nt][e] = 0.0f;

#pragma unroll
  for (int ks = 0; ks < 4; ks++) {
    uint32_t ah4[4];
    ldm4(ah4, sb + SWZ((w * 16 + a_r) * 128 + (ks * 16 + a_k8) * 2));
#pragma unroll
    for (int np = 0; np < 8; np++) {
      uint32_t bh4[4];
      ldm4(bh4, sb + 16384 + SWZ((np * 16 + b_r) * 128 + (ks * 16 + b_k8) * 2));
      mma16816h(acc[2 * np],     ah4, bh4);
      mma16816h(acc[2 * np + 1], ah4, bh4 + 2);
    }
  }

  // ---- in-register gates + c/h update + dx partials --------------------------
  int qr = lane >> 2, qc = lane & 3;
  size_t p0 = bpt + w * 16 + qr;
  float pd[2] = {0.0f, 0.0f};

#pragma unroll
  for (int m = 0; m < 4; m++) {
#pragma unroll
    for (int rh = 0; rh < 2; rh++) {
      size_t pt = p0 + 8 * rh;
      int ob = 8 * m + 2 * qc;
      float2 cold = make_float2(0.0f, 0.0f);
      if (!first) {
        __half2 ch = *(const __half2*)&c16[pt * 32 + ob];
        cold.x = __half2float(ch.x);
        cold.y = __half2float(ch.y);
      }
      float cn[2], hn[2];
#pragma unroll
      for (int p = 0; p < 2; p++) {
        int o = ob + p;
        int e = p + 2 * rh;
        float zi = acc[4 + m][e]  + sbg[32 + o];
        float zc = acc[12 + m][e] + sbg[96 + o];
        float cnew = sigf(zi) * sigf(zc);
        if (!first) {
          float zf = acc[m][e] + sbg[o];
          cnew += sigf(zf) * (p ? cold.y : cold.x);
        }
        cn[p] = cnew;
        pd[rh] += cnew * swo[o];
        if (!last) {
          float zo = acc[8 + m][e] + sbg[64 + o];
          hn[p] = sigf(zo) * sigf(cnew);
        }
      }
      if (!last) {
        *(uint32_t*)&c16[pt * 32 + ob] =
            pack2h(__float2half(cn[0]), __float2half(cn[1]));
        *(uint32_t*)&h16_g[pt * 32 + ob] =
            pack2h(__float2half(hn[0]), __float2half(hn[1]));
      }
    }
  }

#pragma unroll
  for (int rh = 0; rh < 2; rh++) {
    pd[rh] += __shfl_xor_sync(0xFFFFFFFF, pd[rh], 1);
    pd[rh] += __shfl_xor_sync(0xFFFFFFFF, pd[rh], 2);
  }
  if (qc == 0) {
    float b0 = __ldg(bout);
#pragma unroll
    for (int rh = 0; rh < 2; rh++) {
      size_t gi = p0 + 8 * rh;
      float xn = x[gi] + tanhf(pd[rh] + b0);
      x[gi] = xn;
      if (!last) {
        __half xh = __float2half(xn);
        xf16[gi] = xh;
        int row = (int)(gi / ND);
        int col = (int)(gi - (size_t)row * ND);
        xT16[(ll)col * ND + row] = xh;
      }
    }
  }
}

// ---------------- orchestration ----------------------------------------------
extern "C" void kernel_launch(void* const* d_in, const int* in_sizes, int n_in,
                              void* d_out, int out_size)
{
  const float* x     = (const float*)d_in[0];
  const float* L_row = (const float*)d_in[1];
  const float* L_col = (const float*)d_in[2];
  const float* theta = (const float*)d_in[3];
  const float* bias  = (const float*)d_in[4];
  const float* W_f = (const float*)d_in[5];
  const float* U_f = (const float*)d_in[6];
  const float* b_f = (const float*)d_in[7];
  const float* W_i = (const float*)d_in[8];
  const float* U_i = (const float*)d_in[9];
  const float* b_i = (const float*)d_in[10];
  const float* W_o = (const float*)d_in[11];
  const float* U_o = (const float*)d_in[12];
  const float* b_o = (const float*)d_in[13];
  const float* W_c = (const float*)d_in[14];
  const float* U_c = (const float*)d_in[15];
  const float* b_c = (const float*)d_in[16];
  const float* W_out = (const float*)d_in[17];
  const float* b_out = (const float*)d_in[18];
  // d_in[19] = nb_iterations_rnn = 3 (fixed by setup)

  float* xcur = (float*)d_out;

  float *Tf;
  __nv_bfloat16 *Tsh, *Tsl;
  __half *Tf16, *xT16, *Y16, *bf16, *h16, *c16, *Wt16;
  cudaGetSymbolAddress((void**)&Tf,   g_Tf);
  cudaGetSymbolAddress((void**)&Tsh,  g_Tsh);
  cudaGetSymbolAddress((void**)&Tsl,  g_Tsl);
  cudaGetSymbolAddress((void**)&Tf16, g_Tf16);
  cudaGetSymbolAddress((void**)&xT16, g_xT16);
  cudaGetSymbolAddress((void**)&Y16,  g_Y16);
  cudaGetSymbolAddress((void**)&bf16, g_bf16);
  cudaGetSymbolAddress((void**)&h16,  g_h16);
  cudaGetSymbolAddress((void**)&c16,  g_c16);
  cudaGetSymbolAddress((void**)&Wt16, g_Wt16);

  const ll S = SZ;
  const int DSM_CHEB = 1024 + 3 * 49152;               // bf16 3-term, 48KB stages
  const int DSM_Y    = 1024 + 3 * ((64 + 128) * 128);  // fp16, 24KB stages
  const int DSM_BF   = 1024 + 3 * ((128 + 128) * 128); // fp16, 32KB stages
  const int FSM      = 1024 + 32768 + 3968;
  cudaFuncSetAttribute((const void*)tc_gemm_cheb,   cudaFuncAttributeMaxDynamicSharedMemorySize, DSM_CHEB);
  cudaFuncSetAttribute((const void*)tc_gemm16<64>,  cudaFuncAttributeMaxDynamicSharedMemorySize, DSM_Y);
  cudaFuncSetAttribute((const void*)tc_gemm16<128>, cudaFuncAttributeMaxDynamicSharedMemorySize, DSM_BF);
  cudaFuncSetAttribute((const void*)fused_rnn,      cudaFuncAttributeMaxDynamicSharedMemorySize, FSM);

  // launch 1: merged setup
  {
    dim3 g(SZ / 1024, 1, 5);
    setup_kernel<<<g, 256>>>(L_row, L_col, Tf, Tsh, Tsl, Tf16,
                             x, xcur, Y16, xT16,
                             W_f, U_f, W_i, U_i, W_o, U_o, W_c, U_c, Wt16);
  }

  // Chebyshev recursion (bf16 3-term; emits fp32 + bf16 split + fp16)
  for (int k = 2; k <= 4; k++) {
    dim3 g(6, 12, 2);
    int cinmode = (k == 2) ? 1 : 2;
    const float* cin = (k == 2) ? (const float*)0 : (Tf + (ll)(k - 2) * S);
    tc_gemm_cheb<<<g, 256, DSM_CHEB>>>(
        Tsh + S, Tsl + S,
        Tsh + (ll)(k - 1) * S, Tsl + (ll)(k - 1) * S,
        cin, Tf + (ll)k * S, Tsh + (ll)k * S, Tsl + (ll)k * S, Tf16 + (ll)k * S,
        5 * S, 5 * S, 5 * S, 5 * S, 2.0f, -1.0f, cinmode);
  }

  for (int it = 0; it < 3; it++) {
    // Y_{1+z} = Tr_{1+z} @ x   (fp16 single-term, fp16 out)
    {
      dim3 g(6, 12, 4);
      tc_gemm16<64><<<g, 256, DSM_Y>>>(
          Tf16 + S, xT16, Y16 + S,
          S, 0, 1,    0, 0, 1,    S);
    }
    // bf[z] = Y_{z/4} @ Tc_{1+z%4}   (fp16 single-term, fp16 out)
    {
      dim3 g(6, 6, 20);
      tc_gemm16<128><<<g, 256, DSM_BF>>>(
          Y16, Tf16 + 6 * S, bf16,
          0, S, 4,    0, S, 4,    S);
    }
    fused_rnn<<<SZ / 128, 256, FSM>>>(
        Y16, bf16, theta, bias, Wt16,
        b_f, b_i, b_o, b_c, W_out, b_out,
        c16, h16, xcur, Y16, xT16,
        (it == 0) ? 1 : 0, (it == 2) ? 1 : 0);
  }
}

// round 15
// speedup vs baseline: 1.6732x; 1.0323x over previous
#include <cuda_runtime.h>
#include <cuda_bf16.h>
#include <cuda_fp16.h>
#include <cstdint>

#define ND 768
#define SZ (768*768)
#define MNTOT SZ
typedef long long ll;

// ---------------- scratch (device globals) ----------------------------------
__device__ __align__(16) __nv_bfloat16 g_Tsh[10*SZ];  // bf16 hi (cheb)
__device__ __align__(16) __nv_bfloat16 g_Tsl[10*SZ];  // bf16 lo (cheb)
__device__ __align__(16) __half g_Tf16[10*SZ];        // fp16 T (Y/bf operands)
__device__ __align__(16) __half g_xT16[SZ];           // fp16 x^T
__device__ __align__(16) __half g_Y16[5*SZ];          // slot0 = x fp16; 1..4 = Y_i
__device__ __align__(16) __half g_bf16[20*SZ];        // bf products fp16
__device__ __align__(16) __half g_h16[32*SZ];         // h point-major [pt][32] fp16
__device__ __align__(16) __half g_c16[32*SZ];         // c point-major [pt][32] fp16
__device__ __align__(16) __half g_Wt16[128*64];       // [n=g*32+o][k] fp16

// ---------------- helpers -----------------------------------------------------
#define SWZ(x)   ((x) ^ (((x) >> 3) & 0x70))   // 128B rows

__device__ __forceinline__ uint32_t smem_u32(const void* p) {
  uint32_t a;
  asm("{ .reg .u64 t; cvta.to.shared.u64 t, %1; cvt.u32.u64 %0, t; }"
      : "=r"(a) : "l"(p));
  return a;
}

__device__ __forceinline__ void cpa16(uint32_t dst, const void* src) {
  asm volatile("cp.async.cg.shared.global [%0], [%1], 16;"
               :: "r"(dst), "l"(src) : "memory");
}
__device__ __forceinline__ void cpa16_ca(uint32_t dst, const void* src) {
  asm volatile("cp.async.ca.shared.global [%0], [%1], 16;"
               :: "r"(dst), "l"(src) : "memory");
}
#define CP_COMMIT() asm volatile("cp.async.commit_group;" ::: "memory")
#define CP_WAIT(n)  asm volatile("cp.async.wait_group %0;" :: "n"(n) : "memory")

__device__ __forceinline__ void ldm4(uint32_t* r, uint32_t addr) {
  asm volatile("ldmatrix.sync.aligned.m8n8.x4.shared.b16 {%0,%1,%2,%3}, [%4];"
               : "=r"(r[0]), "=r"(r[1]), "=r"(r[2]), "=r"(r[3]) : "r"(addr));
}

__device__ __forceinline__ void mma16816(float* c, const uint32_t* a,
                                         const uint32_t* b) {
  asm volatile(
      "mma.sync.aligned.m16n8k16.row.col.f32.bf16.bf16.f32 "
      "{%0,%1,%2,%3},{%4,%5,%6,%7},{%8,%9},{%0,%1,%2,%3};"
      : "+f"(c[0]), "+f"(c[1]), "+f"(c[2]), "+f"(c[3])
      : "r"(a[0]), "r"(a[1]), "r"(a[2]), "r"(a[3]), "r"(b[0]), "r"(b[1]));
}

__device__ __forceinline__ void mma16816h(float* c, const uint32_t* a,
                                          const uint32_t* b) {
  asm volatile(
      "mma.sync.aligned.m16n8k16.row.col.f32.f16.f16.f32 "
      "{%0,%1,%2,%3},{%4,%5,%6,%7},{%8,%9},{%0,%1,%2,%3};"
      : "+f"(c[0]), "+f"(c[1]), "+f"(c[2]), "+f"(c[3])
      : "r"(a[0]), "r"(a[1]), "r"(a[2]), "r"(a[3]), "r"(b[0]), "r"(b[1]));
}

__device__ __forceinline__ uint32_t pack2(__nv_bfloat16 a, __nv_bfloat16 b) {
  __nv_bfloat162 t(a, b);
  return *reinterpret_cast<uint32_t*>(&t);
}
__device__ __forceinline__ uint32_t pack2h(__half a, __half b) {
  __half2 t(a, b);
  return *reinterpret_cast<uint32_t*>(&t);
}

__device__ __forceinline__ float tanhap(float v) {
  float t;
  asm("tanh.approx.f32 %0, %1;" : "=f"(t) : "f"(v));
  return t;
}
__device__ __forceinline__ float sigf(float v) {
  return fmaf(0.5f, tanhap(0.5f * v), 0.5f);
}

// ================= bf16 3-term GEMM (Chebyshev only) =========================
__device__ __forceinline__ void load_chunk_b(
    uint32_t sb, int s, int kc, int tid, int brow, int bcol,
    const __nv_bfloat16* a0, const __nv_bfloat16* a1,
    const __nv_bfloat16* b0, const __nv_bfloat16* b1)
{
  constexpr int ASTAGE = 64 * 128;
  constexpr int BSTAGE = 128 * 128;
  constexpr int STAGE  = 2 * ASTAGE + 2 * BSTAGE;   // 48 KB
#pragma unroll
  for (int i = 0; i < 12; i++) {
    int idx = tid + i * 256;
    int cc = idx & 7;
    int rowIdx = idx >> 3;
    const __nv_bfloat16* src;
    uint32_t dstbase;
    if (rowIdx < 128) {
      int mat = rowIdx >> 6;
      int row = rowIdx & 63;
      src = (mat ? a1 : a0) + (ll)(brow + row) * ND + kc * 64 + cc * 8;
      dstbase = mat * ASTAGE + SWZ(row * 128 + cc * 16);
    } else {
      int rr = rowIdx - 128;
      int mat = rr >> 7;
      int row = rr & 127;
      src = (mat ? b1 : b0) + (ll)(bcol + row) * ND + kc * 64 + cc * 8;
      dstbase = 2 * ASTAGE + mat * BSTAGE + SWZ(row * 128 + cc * 16);
    }
    cpa16(sb + s * STAGE + dstbase, src);
  }
}

__global__ __launch_bounds__(256, 1) void tc_gemm_cheb(
    const __nv_bfloat16* __restrict__ Ah, const __nv_bfloat16* __restrict__ Al,
    const __nv_bfloat16* __restrict__ Bh, const __nv_bfloat16* __restrict__ Bl,
    const __nv_bfloat16* __restrict__ Cinh, const __nv_bfloat16* __restrict__ Cinl,
    __nv_bfloat16* __restrict__ Couth, __nv_bfloat16* __restrict__ Coutl,
    __half* __restrict__ Coutf16,
    ll sAz, ll sBz, ll sCinz, ll sCz, float alpha, float beta, int cinmode)
{
  extern __shared__ char dsm[];
  constexpr int ASTAGE = 64 * 128;
  constexpr int BSTAGE = 128 * 128;
  constexpr int STAGE  = 2 * ASTAGE + 2 * BSTAGE;

  int z = blockIdx.z;
  const __nv_bfloat16* ah = Ah + sAz * z;
  const __nv_bfloat16* al = Al + sAz * z;
  const __nv_bfloat16* bh = Bh + sBz * z;
  const __nv_bfloat16* bl = Bl + sBz * z;
  const int brow = blockIdx.y * 64;
  const int bcol = blockIdx.x * 128;

  int tid = threadIdx.x;
  int lane = tid & 31;
  int wid = tid >> 5;
  int wrow = (wid & 1) * 32;
  int wcol = (wid >> 1) * 32;

  uint32_t raw = smem_u32(dsm);
  uint32_t sb = (raw + 1023) & ~1023u;

  float acc[2][4][4];
#pragma unroll
  for (int mi = 0; mi < 2; mi++)
#pragma unroll
    for (int ni = 0; ni < 4; ni++)
#pragma unroll
      for (int e = 0; e < 4; e++) acc[mi][ni][e] = 0.0f;

  int a_r  = (lane & 7) + ((lane >> 3) & 1) * 8;
  int a_k8 = ((lane >> 4) & 1) * 8;
  int b_r  = (lane & 7) + ((lane >> 4) & 1) * 8;
  int b_k8 = ((lane >> 3) & 1) * 8;

  load_chunk_b(sb, 0, 0, tid, brow, bcol, ah, al, bh, bl); CP_COMMIT();
  load_chunk_b(sb, 1, 1, tid, brow, bcol, ah, al, bh, bl); CP_COMMIT();

  for (int kc = 0; kc < 12; kc++) {
    if (kc < 11) { CP_WAIT(1); } else { CP_WAIT(0); }
    __syncthreads();

    uint32_t st  = sb + (kc % 3) * STAGE;
    uint32_t tAh = st;
    uint32_t tAl = st + ASTAGE;
    uint32_t tBh = st + 2 * ASTAGE;
    uint32_t tBl = tBh + BSTAGE;

#pragma unroll
    for (int s = 0; s < 4; s++) {
      uint32_t fah[2][4], fal[2][4];
#pragma unroll
      for (int mi = 0; mi < 2; mi++) {
        int r = wrow + mi * 16 + a_r;
        uint32_t off = SWZ(r * 128 + (s * 16 + a_k8) * 2);
        ldm4(fah[mi], tAh + off);
        ldm4(fal[mi], tAl + off);
      }
      uint32_t fbh[4][2], fbl[4][2];
#pragma unroll
      for (int nj2 = 0; nj2 < 2; nj2++) {
        int r = wcol + nj2 * 16 + b_r;
        uint32_t off = SWZ(r * 128 + (s * 16 + b_k8) * 2);
        uint32_t t4[4];
        ldm4(t4, tBh + off);
        fbh[nj2 * 2][0] = t4[0]; fbh[nj2 * 2][1] = t4[1];
        fbh[nj2 * 2 + 1][0] = t4[2]; fbh[nj2 * 2 + 1][1] = t4[3];
        ldm4(t4, tBl + off);
        fbl[nj2 * 2][0] = t4[0]; fbl[nj2 * 2][1] = t4[1];
        fbl[nj2 * 2 + 1][0] = t4[2]; fbl[nj2 * 2 + 1][1] = t4[3];
      }
#pragma unroll
      for (int mi = 0; mi < 2; mi++)
#pragma unroll
        for (int nl = 0; nl < 4; nl++)
          mma16816(acc[mi][nl], fah[mi], fbh[nl]);
#pragma unroll
      for (int mi = 0; mi < 2; mi++)
#pragma unroll
        for (int nl = 0; nl < 4; nl++)
          mma16816(acc[mi][nl], fah[mi], fbl[nl]);
#pragma unroll
      for (int mi = 0; mi < 2; mi++)
#pragma unroll
        for (int nl = 0; nl < 4; nl++)
          mma16816(acc[mi][nl], fal[mi], fbh[nl]);
    }

    if (kc + 2 < 12) {
      load_chunk_b(sb, (kc + 2) % 3, kc + 2, tid, brow, bcol, ah, al, bh, bl);
      CP_COMMIT();
    }
  }

  const __nv_bfloat16* cinh = (cinmode == 2) ? (Cinh + sCinz * z) : (const __nv_bfloat16*)0;
  const __nv_bfloat16* cinl = (cinmode == 2) ? (Cinl + sCinz * z) : (const __nv_bfloat16*)0;
  __nv_bfloat16* coh = Couth + sCz * z;
  __nv_bfloat16* col = Coutl + sCz * z;
  __half* cof = Coutf16 + sCz * z;
  int qr = lane >> 2, qc = lane & 3;

#pragma unroll
  for (int mi = 0; mi < 2; mi++) {
#pragma unroll
    for (int ni = 0; ni < 4; ni++) {
      int gr0 = brow + wrow + mi * 16 + qr;
      int gc  = bcol + wcol + ni * 8 + qc * 2;
      float2 v0, v1;
      v0.x = alpha * acc[mi][ni][0];
      v0.y = alpha * acc[mi][ni][1];
      v1.x = alpha * acc[mi][ni][2];
      v1.y = alpha * acc[mi][ni][3];
      if (cinmode == 2) {
        // reconstruct fp32 Cin from bf16 hi + lo
        __nv_bfloat162 h0 = *(const __nv_bfloat162*)&cinh[(ll)gr0 * ND + gc];
        __nv_bfloat162 l0 = *(const __nv_bfloat162*)&cinl[(ll)gr0 * ND + gc];
        __nv_bfloat162 h1 = *(const __nv_bfloat162*)&cinh[(ll)(gr0 + 8) * ND + gc];
        __nv_bfloat162 l1 = *(const __nv_bfloat162*)&cinl[(ll)(gr0 + 8) * ND + gc];
        v0.x += beta * (__bfloat162float(h0.x) + __bfloat162float(l0.x));
        v0.y += beta * (__bfloat162float(h0.y) + __bfloat162float(l0.y));
        v1.x += beta * (__bfloat162float(h1.x) + __bfloat162float(l1.x));
        v1.y += beta * (__bfloat162float(h1.y) + __bfloat162float(l1.y));
      } else if (cinmode == 1) {
        if (gr0 == gc)         v0.x += beta;
        if (gr0 == gc + 1)     v0.y += beta;
        if (gr0 + 8 == gc)     v1.x += beta;
        if (gr0 + 8 == gc + 1) v1.y += beta;
      }
      __nv_bfloat16 h0 = __float2bfloat16(v0.x);
      __nv_bfloat16 h1 = __float2bfloat16(v0.y);
      __nv_bfloat16 h2 = __float2bfloat16(v1.x);
      __nv_bfloat16 h3 = __float2bfloat16(v1.y);
      *(uint32_t*)&coh[(ll)gr0 * ND + gc]       = pack2(h0, h1);
      *(uint32_t*)&coh[(ll)(gr0 + 8) * ND + gc] = pack2(h2, h3);
      *(uint32_t*)&col[(ll)gr0 * ND + gc] =
          pack2(__float2bfloat16(v0.x - __bfloat162float(h0)),
                __float2bfloat16(v0.y - __bfloat162float(h1)));
      *(uint32_t*)&col[(ll)(gr0 + 8) * ND + gc] =
          pack2(__float2bfloat16(v1.x - __bfloat162float(h2)),
                __float2bfloat16(v1.y - __bfloat162float(h3)));
      *(uint32_t*)&cof[(ll)gr0 * ND + gc] =
          pack2h(__float2half(v0.x), __float2half(v0.y));
      *(uint32_t*)&cof[(ll)(gr0 + 8) * ND + gc] =
          pack2h(__float2half(v1.x), __float2half(v1.y));
    }
  }
}

// ================= fp16 single-term GEMM (Y and bf) ==========================
template<int TM>
__device__ __forceinline__ void load_chunk_h(
    uint32_t sb, int s, int kc, int tid, int brow, int bcol,
    const __half* a, const __half* b)
{
  constexpr int ASTAGE = TM * 128;
  constexpr int STAGE  = ASTAGE + 128 * 128;
  constexpr int ITER   = (TM + 128) * 8 / 256;
#pragma unroll
  for (int i = 0; i < ITER; i++) {
    int idx = tid + i * 256;
    int cc = idx & 7;
    int rowIdx = idx >> 3;
    const __half* src;
    uint32_t dstbase;
    if (rowIdx < TM) {
      src = a + (ll)(brow + rowIdx) * ND + kc * 64 + cc * 8;
      dstbase = SWZ(rowIdx * 128 + cc * 16);
    } else {
      int row = rowIdx - TM;
      src = b + (ll)(bcol + row) * ND + kc * 64 + cc * 8;
      dstbase = ASTAGE + SWZ(row * 128 + cc * 16);
    }
    cpa16(sb + s * STAGE + dstbase, src);
  }
}

template<int TM>
__global__ __launch_bounds__(256, 2) void tc_gemm16(
    const __half* __restrict__ A, const __half* __restrict__ B,
    __half* __restrict__ Coutf16,
    ll sAz, ll sAdiv, int adiv,
    ll sBz, ll sBmod, int bmod, ll sCz)
{
  extern __shared__ char dsm[];
  constexpr int ASTAGE = TM * 128;
  constexpr int STAGE  = ASTAGE + 128 * 128;
  constexpr int NI = (TM == 128) ? 8 : 4;
  constexpr int NPAIR = NI / 4;

  int z = blockIdx.z;
  const __half* a = A + sAz * z + sAdiv * (z / adiv);
  const __half* b = B + sBz * z + sBmod * (z % bmod);
  const int brow = blockIdx.y * TM;
  const int bcol = blockIdx.x * 128;

  int tid = threadIdx.x;
  int lane = tid & 31;
  int wid = tid >> 5;
  int wrow, wcol;
  if (TM == 128) { wrow = (wid & 3) * 32; wcol = (wid >> 2) * 64; }
  else           { wrow = (wid & 1) * 32; wcol = (wid >> 1) * 32; }

  uint32_t raw = smem_u32(dsm);
  uint32_t sb = (raw + 1023) & ~1023u;

  float acc[2][NI][4];
#pragma unroll
  for (int mi = 0; mi < 2; mi++)
#pragma unroll
    for (int ni = 0; ni < NI; ni++)
#pragma unroll
      for (int e = 0; e < 4; e++) acc[mi][ni][e] = 0.0f;

  int a_r  = (lane & 7) + ((lane >> 3) & 1) * 8;
  int a_k8 = ((lane >> 4) & 1) * 8;
  int b_r  = (lane & 7) + ((lane >> 4) & 1) * 8;
  int b_k8 = ((lane >> 3) & 1) * 8;

  load_chunk_h<TM>(sb, 0, 0, tid, brow, bcol, a, b); CP_COMMIT();
  load_chunk_h<TM>(sb, 1, 1, tid, brow, bcol, a, b); CP_COMMIT();

  for (int kc = 0; kc < 12; kc++) {
    if (kc < 11) { CP_WAIT(1); } else { CP_WAIT(0); }
    __syncthreads();

    uint32_t st = sb + (kc % 3) * STAGE;
    uint32_t tA = st;
    uint32_t tB = st + ASTAGE;

#pragma unroll
    for (int s = 0; s < 4; s++) {
      uint32_t fa[2][4];
#pragma unroll
      for (int mi = 0; mi < 2; mi++) {
        int r = wrow + mi * 16 + a_r;
        ldm4(fa[mi], tA + SWZ(r * 128 + (s * 16 + a_k8) * 2));
      }
#pragma unroll
      for (int p = 0; p < NPAIR; p++) {
        uint32_t fb[4][2];
#pragma unroll
        for (int nj2 = 0; nj2 < 2; nj2++) {
          int r = wcol + (p * 2 + nj2) * 16 + b_r;
          uint32_t t4[4];
          ldm4(t4, tB + SWZ(r * 128 + (s * 16 + b_k8) * 2));
          fb[nj2 * 2][0] = t4[0]; fb[nj2 * 2][1] = t4[1];
          fb[nj2 * 2 + 1][0] = t4[2]; fb[nj2 * 2 + 1][1] = t4[3];
        }
#pragma unroll
        for (int mi = 0; mi < 2; mi++)
#pragma unroll
          for (int nl = 0; nl < 4; nl++)
            mma16816h(acc[mi][p * 4 + nl], fa[mi], fb[nl]);
      }
    }

    if (kc + 2 < 12) {
      load_chunk_h<TM>(sb, (kc + 2) % 3, kc + 2, tid, brow, bcol, a, b);
      CP_COMMIT();
    }
  }

  __half* cof = Coutf16 + sCz * z;
  int qr = lane >> 2, qc = lane & 3;

#pragma unroll
  for (int mi = 0; mi < 2; mi++) {
#pragma unroll
    for (int ni = 0; ni < NI; ni++) {
      int gr0 = brow + wrow + mi * 16 + qr;
      int gc  = bcol + wcol + ni * 8 + qc * 2;
      *(uint32_t*)&cof[(ll)gr0 * ND + gc] =
          pack2h(__float2half(acc[mi][ni][0]), __float2half(acc[mi][ni][1]));
      *(uint32_t*)&cof[(ll)(gr0 + 8) * ND + gc] =
          pack2h(__float2half(acc[mi][ni][2]), __float2half(acc[mi][ni][3]));
    }
  }
}

// ---------------- merged setup (single launch) -------------------------------
__global__ __launch_bounds__(256) void setup_kernel(
    const float* __restrict__ L_row, const float* __restrict__ L_col,
    __nv_bfloat16* __restrict__ Tsh, __nv_bfloat16* __restrict__ Tsl,
    __half* __restrict__ Tf16,
    const float* __restrict__ x, float* __restrict__ xcur,
    __half* __restrict__ Y16, __half* __restrict__ xT16,
    const float* __restrict__ Wf, const float* __restrict__ Uf,
    const float* __restrict__ Wi, const float* __restrict__ Ui,
    const float* __restrict__ Wo, const float* __restrict__ Uo,
    const float* __restrict__ Wc, const float* __restrict__ Uc,
    __half* __restrict__ Wt16)
{
  __shared__ float ts[32][33];
  int z = blockIdx.z;
  int t = threadIdx.x;

  if (z == 3) {
    if (blockIdx.x >= 32) return;
    const float* Ws[4] = {Wf, Wi, Wo, Wc};
    const float* Us[4] = {Uf, Ui, Uo, Uc};
    int idx = blockIdx.x * 256 + t;
    int n = idx >> 6, k = idx & 63;
    int g = n >> 5, o = n & 31;
    float v = (k < 32) ? Ws[g][k * 32 + o] : Us[g][(k - 32) * 32 + o];
    Wt16[idx] = __float2half(v);
    return;
  }
  if (z == 4) {
    int bx = (blockIdx.x % 24) * 32, by = (blockIdx.x / 24) * 32;
    int tx = t & 31, ty = t >> 5;
#pragma unroll
    for (int i = 0; i < 4; i++)
      ts[ty + 8 * i][tx] = x[(ll)(by + ty + 8 * i) * ND + bx + tx];
    __syncthreads();
#pragma unroll
    for (int i = 0; i < 4; i++)
      xT16[(ll)(bx + ty + 8 * i) * ND + by + tx] = __float2half(ts[tx][ty + 8 * i]);
    return;
  }
  if (z == 2) {
    int idx = blockIdx.x * 256 + t;
    float4 v = *(const float4*)(x + (ll)idx * 4);
    *(float4*)(xcur + (ll)idx * 4) = v;
    uint2 uf;
    uf.x = pack2h(__float2half(v.x), __float2half(v.y));
    uf.y = pack2h(__float2half(v.z), __float2half(v.w));
    *(uint2*)(Y16 + (ll)idx * 4) = uf;
    return;
  }

  const float* src = (z == 0) ? L_row : L_col;
  ll off = (z == 0) ? (ll)SZ : (ll)6 * SZ;
  int idx = blockIdx.x * 256 + t;
  float4 v = *(const float4*)(src + (ll)idx * 4);
  float a[4] = {v.x, v.y, v.z, v.w};
  __nv_bfloat16 h[4];
  uint2 uh, ul, uf;
#pragma unroll
  for (int e = 0; e < 4; e++) h[e] = __float2bfloat16(a[e]);
  uh.x = pack2(h[0], h[1]); uh.y = pack2(h[2], h[3]);
  ul.x = pack2(__float2bfloat16(a[0] - __bfloat162float(h[0])),
               __float2bfloat16(a[1] - __bfloat162float(h[1])));
  ul.y = pack2(__float2bfloat16(a[2] - __bfloat162float(h[2])),
               __float2bfloat16(a[3] - __bfloat162float(h[3])));
  uf.x = pack2h(__float2half(a[0]), __float2half(a[1]));
  uf.y = pack2h(__float2half(a[2]), __float2half(a[3]));
  *(uint2*)(Tsh + off + (ll)idx * 4) = uh;
  *(uint2*)(Tsl + off + (ll)idx * 4) = ul;
  *(uint2*)(Tf16 + off + (ll)idx * 4) = uf;
}

// ---------------- fused_rnn v9: hw-tanh sigmoids -----------------------------
__global__ __launch_bounds__(256, 2) void fused_rnn(
    const __half* __restrict__ Y16_g, const __half* __restrict__ bf16_g,
    const float* __restrict__ theta, const float* __restrict__ bias,
    const __half* __restrict__ Wt16,
    const float* __restrict__ bf_, const float* __restrict__ bi_,
    const float* __restrict__ bo_, const float* __restrict__ bc_,
    const float* __restrict__ Wout, const float* __restrict__ bout,
    __half* c16, __half* h16_g, float* x,
    __half* __restrict__ xf16, __half* __restrict__ xT16,
    int first, int last)
{
  extern __shared__ char dsm[];
  uint32_t raw = smem_u32(dsm);
  uint32_t sb = (raw + 1023) & ~1023u;
  char* base = dsm + (sb - raw);

  float* th  = (float*)(base + 32768);
  float* bs  = (float*)(base + 32768 + 3200);
  float* swo = (float*)(base + 32768 + 3328);
  float* sbg = (float*)(base + 32768 + 3456);

  int t = threadIdx.x;
  int lane = t & 31;
  int w = t >> 5;
  size_t bpt = (size_t)blockIdx.x * 128;

  // ---- cp.async: W tile (.ca) + h rows ---------------------------------------
#pragma unroll
  for (int i = 0; i < 4; i++) {
    int idx = t + i * 256;
    int rr  = idx >> 3;
    int c4  = idx & 7;
    cpa16_ca(sb + 16384 + SWZ(rr * 128 + c4 * 16), Wt16 + rr * 64 + c4 * 8);
  }
  if (!first) {
#pragma unroll
    for (int i = 0; i < 2; i++) {
      int idx = t + i * 256;
      int rr  = idx >> 2;
      int c4h = (idx & 3) + 4;
      cpa16(sb + SWZ(rr * 128 + c4h * 16),
            h16_g + (bpt + rr) * 32 + (c4h - 4) * 8);
    }
  } else {
    uint4 z4 = make_uint4(0, 0, 0, 0);
#pragma unroll
    for (int i = 0; i < 2; i++) {
      int idx = t + i * 256;
      int rr  = idx >> 2;
      int c4h = (idx & 3) + 4;
      *(uint4*)(base + SWZ(rr * 128 + c4h * 16)) = z4;
    }
  }
  CP_COMMIT();

  // ---- prefetch 25 conv-source values (fp16, before any sync) ----------------
  int r   = t & 127;
  int ohp = (t >> 7) * 16;
  size_t rg = bpt + r;
  float v[25];
#pragma unroll
  for (int i = 0; i < 5; i++)
    v[i * 5] = __half2float(__ldg(Y16_g + (ll)i * SZ + rg));
#pragma unroll
  for (int i = 0; i < 5; i++)
#pragma unroll
    for (int j = 1; j < 5; j++)
      v[i * 5 + j] = __half2float(__ldg(bf16_g + (ll)(i * 4 + j - 1) * SZ + rg));

  // ---- scalars ---------------------------------------------------------------
  for (int i = t; i < 800; i += 256) th[i] = theta[i];
  if (t < 32) { bs[t] = bias[t]; swo[t] = Wout[t]; }
  if (t < 128) { const float* bx[4] = {bf_, bi_, bo_, bc_}; sbg[t] = bx[t >> 5][t & 31]; }
  __syncthreads();

  // ---- combine -> A cols 0..31 (xc fp16) -------------------------------------
  {
    float out[16];
#pragma unroll
    for (int o = 0; o < 16; o++) out[o] = bs[ohp + o];
#pragma unroll
    for (int ij = 0; ij < 25; ij++) {
      const float* tw = &th[ij * 32 + ohp];
#pragma unroll
      for (int o = 0; o < 16; o++) out[o] += v[ij] * tw[o];
    }
#pragma unroll
    for (int i = 0; i < 8; i++) {
      uint32_t byte = r * 128 + (ohp + 2 * i) * 2;
      *(uint32_t*)(base + SWZ(byte)) =
          pack2h(__float2half(out[2 * i]), __float2half(out[2 * i + 1]));
    }
  }
  CP_WAIT(0);
  __syncthreads();

  // ---- HMMA: PRE[128 pt x 128 n] = A @ W^T (fp16 single-term) ----------------
  int a_r  = (lane & 7) + ((lane >> 3) & 1) * 8;
  int a_k8 = ((lane >> 4) & 1) * 8;
  int b_r  = (lane & 7) + ((lane >> 4) & 1) * 8;
  int b_k8 = ((lane >> 3) & 1) * 8;

  float acc[16][4];
#pragma unroll
  for (int nt = 0; nt < 16; nt++)
#pragma unroll
    for (int e = 0; e < 4; e++) acc[nt][e] = 0.0f;

#pragma unroll
  for (int ks = 0; ks < 4; ks++) {
    uint32_t ah4[4];
    ldm4(ah4, sb + SWZ((w * 16 + a_r) * 128 + (ks * 16 + a_k8) * 2));
#pragma unroll
    for (int np = 0; np < 8; np++) {
      uint32_t bh4[4];
      ldm4(bh4, sb + 16384 + SWZ((np * 16 + b_r) * 128 + (ks * 16 + b_k8) * 2));
      mma16816h(acc[2 * np],     ah4, bh4);
      mma16816h(acc[2 * np + 1], ah4, bh4 + 2);
    }
  }

  // ---- in-register gates + c/h update + dx partials --------------------------
  int qr = lane >> 2, qc = lane & 3;
  size_t p0 = bpt + w * 16 + qr;
  float pd[2] = {0.0f, 0.0f};

#pragma unroll
  for (int m = 0; m < 4; m++) {
#pragma unroll
    for (int rh = 0; rh < 2; rh++) {
      size_t pt = p0 + 8 * rh;
      int ob = 8 * m + 2 * qc;
      float2 cold = make_float2(0.0f, 0.0f);
      if (!first) {
        __half2 ch = *(const __half2*)&c16[pt * 32 + ob];
        cold.x = __half2float(ch.x);
        cold.y = __half2float(ch.y);
      }
      float cn[2], hn[2];
#pragma unroll
      for (int p = 0; p < 2; p++) {
        int o = ob + p;
        int e = p + 2 * rh;
        float zi = acc[4 + m][e]  + sbg[32 + o];
        float zc = acc[12 + m][e] + sbg[96 + o];
        float cnew = sigf(zi) * sigf(zc);
        if (!first) {
          float zf = acc[m][e] + sbg[o];
          cnew += sigf(zf) * (p ? cold.y : cold.x);
        }
        cn[p] = cnew;
        pd[rh] += cnew * swo[o];
        if (!last) {
          float zo = acc[8 + m][e] + sbg[64 + o];
          hn[p] = sigf(zo) * sigf(cnew);
        }
      }
      if (!last) {
        *(uint32_t*)&c16[pt * 32 + ob] =
            pack2h(__float2half(cn[0]), __float2half(cn[1]));
        *(uint32_t*)&h16_g[pt * 32 + ob] =
            pack2h(__float2half(hn[0]), __float2half(hn[1]));
      }
    }
  }

#pragma unroll
  for (int rh = 0; rh < 2; rh++) {
    pd[rh] += __shfl_xor_sync(0xFFFFFFFF, pd[rh], 1);
    pd[rh] += __shfl_xor_sync(0xFFFFFFFF, pd[rh], 2);
  }
  if (qc == 0) {
    float b0 = __ldg(bout);
#pragma unroll
    for (int rh = 0; rh < 2; rh++) {
      size_t gi = p0 + 8 * rh;
      float xn = x[gi] + tanhap(pd[rh] + b0);
      x[gi] = xn;
      if (!last) {
        __half xh = __float2half(xn);
        xf16[gi] = xh;
        int row = (int)(gi / ND);
        int col = (int)(gi - (size_t)row * ND);
        xT16[(ll)col * ND + row] = xh;
      }
    }
  }
}

// ---------------- orchestration ----------------------------------------------
extern "C" void kernel_launch(void* const* d_in, const int* in_sizes, int n_in,
                              void* d_out, int out_size)
{
  const float* x     = (const float*)d_in[0];
  const float* L_row = (const float*)d_in[1];
  const float* L_col = (const float*)d_in[2];
  const float* theta = (const float*)d_in[3];
  const float* bias  = (const float*)d_in[4];
  const float* W_f = (const float*)d_in[5];
  const float* U_f = (const float*)d_in[6];
  const float* b_f = (const float*)d_in[7];
  const float* W_i = (const float*)d_in[8];
  const float* U_i = (const float*)d_in[9];
  const float* b_i = (const float*)d_in[10];
  const float* W_o = (const float*)d_in[11];
  const float* U_o = (const float*)d_in[12];
  const float* b_o = (const float*)d_in[13];
  const float* W_c = (const float*)d_in[14];
  const float* U_c = (const float*)d_in[15];
  const float* b_c = (const float*)d_in[16];
  const float* W_out = (const float*)d_in[17];
  const float* b_out = (const float*)d_in[18];
  // d_in[19] = nb_iterations_rnn = 3 (fixed by setup)

  float* xcur = (float*)d_out;

  __nv_bfloat16 *Tsh, *Tsl;
  __half *Tf16, *xT16, *Y16, *bf16, *h16, *c16, *Wt16;
  cudaGetSymbolAddress((void**)&Tsh,  g_Tsh);
  cudaGetSymbolAddress((void**)&Tsl,  g_Tsl);
  cudaGetSymbolAddress((void**)&Tf16, g_Tf16);
  cudaGetSymbolAddress((void**)&xT16, g_xT16);
  cudaGetSymbolAddress((void**)&Y16,  g_Y16);
  cudaGetSymbolAddress((void**)&bf16, g_bf16);
  cudaGetSymbolAddress((void**)&h16,  g_h16);
  cudaGetSymbolAddress((void**)&c16,  g_c16);
  cudaGetSymbolAddress((void**)&Wt16, g_Wt16);

  const ll S = SZ;
  const int DSM_CHEB = 1024 + 3 * 49152;               // bf16 3-term, 48KB stages
  const int DSM_Y    = 1024 + 3 * ((64 + 128) * 128);  // fp16, 24KB stages
  const int DSM_BF   = 1024 + 3 * ((128 + 128) * 128); // fp16, 32KB stages
  const int FSM      = 1024 + 32768 + 3968;
  cudaFuncSetAttribute((const void*)tc_gemm_cheb,   cudaFuncAttributeMaxDynamicSharedMemorySize, DSM_CHEB);
  cudaFuncSetAttribute((const void*)tc_gemm16<64>,  cudaFuncAttributeMaxDynamicSharedMemorySize, DSM_Y);
  cudaFuncSetAttribute((const void*)tc_gemm16<128>, cudaFuncAttributeMaxDynamicSharedMemorySize, DSM_BF);
  cudaFuncSetAttribute((const void*)fused_rnn,      cudaFuncAttributeMaxDynamicSharedMemorySize, FSM);

  // launch 1: merged setup
  {
    dim3 g(SZ / 1024, 1, 5);
    setup_kernel<<<g, 256>>>(L_row, L_col, Tsh, Tsl, Tf16,
                             x, xcur, Y16, xT16,
                             W_f, U_f, W_i, U_i, W_o, U_o, W_c, U_c, Wt16);
  }

  // Chebyshev recursion (bf16 3-term; Cin from bf16 splits; emits splits + fp16)
  for (int k = 2; k <= 4; k++) {
    dim3 g(6, 12, 2);
    int cinmode = (k == 2) ? 1 : 2;
    const __nv_bfloat16* cinh = (k == 2) ? (const __nv_bfloat16*)0 : (Tsh + (ll)(k - 2) * S);
    const __nv_bfloat16* cinl = (k == 2) ? (const __nv_bfloat16*)0 : (Tsl + (ll)(k - 2) * S);
    tc_gemm_cheb<<<g, 256, DSM_CHEB>>>(
        Tsh + S, Tsl + S,
        Tsh + (ll)(k - 1) * S, Tsl + (ll)(k - 1) * S,
        cinh, cinl,
        Tsh + (ll)k * S, Tsl + (ll)k * S, Tf16 + (ll)k * S,
        5 * S, 5 * S, 5 * S, 5 * S, 2.0f, -1.0f, cinmode);
  }

  for (int it = 0; it < 3; it++) {
    // Y_{1+z} = Tr_{1+z} @ x   (fp16 single-term, fp16 out)
    {
      dim3 g(6, 12, 4);
      tc_gemm16<64><<<g, 256, DSM_Y>>>(
          Tf16 + S, xT16, Y16 + S,
          S, 0, 1,    0, 0, 1,    S);
    }
    // bf[z] = Y_{z/4} @ Tc_{1+z%4}   (fp16 single-term, fp16 out)
    {
      dim3 g(6, 6, 20);
      tc_gemm16<128><<<g, 256, DSM_BF>>>(
          Y16, Tf16 + 6 * S, bf16,
          0, S, 4,    0, S, 4,    S);
    }
    fused_rnn<<<SZ / 128, 256, FSM>>>(
        Y16, bf16, theta, bias, Wt16,
        b_f, b_i, b_o, b_c, W_out, b_out,
        c16, h16, xcur, Y16, xT16,
        (it == 0) ? 1 : 0, (it == 2) ? 1 : 0);
  }
}